// round 1
// baseline (speedup 1.0000x reference)
#include <cuda_runtime.h>
#include <cuda_bf16.h>
#include <cstdint>

// Problem constants
#define TOK   65536      // B*L
#define BATCH 64
#define SEQL  1024
#define HID   512
#define FF    1024
#define HALF_ 256
#define VOC   32000

// -------- scratch (device globals; no allocation allowed) --------
__device__ float g_buf1[(size_t)TOK * FF];    // relu(e@W1+b1)
__device__ float g_x[(size_t)TOK * HID];      // x -> h (LN in place)
__device__ float g_k[(size_t)TOK * HID];      // [ks | ke] per token
__device__ float g_wproj[HID * HID];          // [sem_w | epi_w]
__device__ float g_bproj[HID];
__device__ float g_invd[(size_t)TOK * 2];     // 1/(||k||^2+eps) per (token, {s,e})
__device__ float g_c[BATCH * HID];            // [cs | ce]

// ============================================================
// Tiled SGEMM: C[M,N] = op(A)[M,K] @ B[K,N] + bias, epilogues.
// BM=BN=128, BK=16, 256 threads, 8x8 per thread (split 4+4 tiles).
// GATHER_A: A row m is embed[seq[m]] (K must equal HID).
// EPI: 0 = relu(acc+bias); 1 = acc+bias+embed[seq[m]][n] (N==HID); 2 = acc+bias
// Requirements: N % 128 == 0, K % 16 == 0. M arbitrary (guarded).
// ============================================================
template<bool GATHER_A, int EPI>
__global__ void __launch_bounds__(256) sgemm_k(
    int M, int N, int K,
    const float* __restrict__ A, const float* __restrict__ Bm,
    const float* __restrict__ bias, float* __restrict__ C,
    const int* __restrict__ seq, const float* __restrict__ embed)
{
    __shared__ float As[16][128];
    __shared__ float Bs[16][128];
    const int tid = threadIdx.x;
    const int bm = blockIdx.y * 128;
    const int bn = blockIdx.x * 128;
    const int tx = tid & 15;        // 0..15
    const int ty = tid >> 4;        // 0..15
    const int row0 = ty * 4, row1 = ty * 4 + 64;
    const int col0 = tx * 4, col1 = tx * 4 + 64;

    float acc[8][8];
#pragma unroll
    for (int i = 0; i < 8; i++)
#pragma unroll
        for (int j = 0; j < 8; j++) acc[i][j] = 0.f;

    const int a_r0 = tid >> 2;          // 0..63
    const int a_c  = (tid & 3) * 4;     // 0,4,8,12
    const int b_r0 = tid >> 5;          // 0..7
    const int b_c  = (tid & 31) * 4;    // 0..124

    for (int k0 = 0; k0 < K; k0 += 16) {
        // ---- load A tile (transposed into As[k][m]) ----
#pragma unroll
        for (int i = 0; i < 2; i++) {
            const int mr = a_r0 + i * 64;
            const int m = bm + mr;
            float4 v = make_float4(0.f, 0.f, 0.f, 0.f);
            if (m < M) {
                const float* ap;
                if (GATHER_A) ap = embed + (size_t)seq[m] * K + (k0 + a_c);
                else          ap = A + (size_t)m * K + (k0 + a_c);
                v = *(const float4*)ap;
            }
            As[a_c + 0][mr] = v.x;
            As[a_c + 1][mr] = v.y;
            As[a_c + 2][mr] = v.z;
            As[a_c + 3][mr] = v.w;
        }
        // ---- load B tile ----
#pragma unroll
        for (int i = 0; i < 2; i++) {
            const int kr = k0 + b_r0 + i * 8;
            float4 v = *(const float4*)(Bm + (size_t)kr * N + bn + b_c);
            *(float4*)&Bs[b_r0 + i * 8][b_c] = v;
        }
        __syncthreads();
        // ---- compute ----
#pragma unroll
        for (int kk = 0; kk < 16; kk++) {
            float4 ra0 = *(const float4*)&As[kk][row0];
            float4 ra1 = *(const float4*)&As[kk][row1];
            float4 rb0 = *(const float4*)&Bs[kk][col0];
            float4 rb1 = *(const float4*)&Bs[kk][col1];
            float ra[8] = {ra0.x, ra0.y, ra0.z, ra0.w, ra1.x, ra1.y, ra1.z, ra1.w};
            float rb[8] = {rb0.x, rb0.y, rb0.z, rb0.w, rb1.x, rb1.y, rb1.z, rb1.w};
#pragma unroll
            for (int i = 0; i < 8; i++)
#pragma unroll
                for (int j = 0; j < 8; j++)
                    acc[i][j] += ra[i] * rb[j];
        }
        __syncthreads();
    }

    // ---- epilogue ----
    float4 bi0 = *(const float4*)&bias[bn + col0];
    float4 bi1 = *(const float4*)&bias[bn + col1];
    const float bb0[4] = {bi0.x, bi0.y, bi0.z, bi0.w};
    const float bb1[4] = {bi1.x, bi1.y, bi1.z, bi1.w};
#pragma unroll
    for (int i = 0; i < 8; i++) {
        const int m = bm + ((i < 4) ? (row0 + i) : (row1 + i - 4));
        if (m >= M) continue;
        float v0[4], v1[4];
#pragma unroll
        for (int j = 0; j < 4; j++) { v0[j] = acc[i][j] + bb0[j]; v1[j] = acc[i][j + 4] + bb1[j]; }
        if (EPI == 0) {
#pragma unroll
            for (int j = 0; j < 4; j++) { v0[j] = fmaxf(v0[j], 0.f); v1[j] = fmaxf(v1[j], 0.f); }
        }
        if (EPI == 1) {
            const size_t er = (size_t)seq[m] * N;   // N == HID here
            float4 e0 = *(const float4*)&embed[er + bn + col0];
            float4 e1 = *(const float4*)&embed[er + bn + col1];
            v0[0] += e0.x; v0[1] += e0.y; v0[2] += e0.z; v0[3] += e0.w;
            v1[0] += e1.x; v1[1] += e1.y; v1[2] += e1.z; v1[3] += e1.w;
        }
        float4 o0 = make_float4(v0[0], v0[1], v0[2], v0[3]);
        float4 o1 = make_float4(v1[0], v1[1], v1[2], v1[3]);
        *(float4*)&C[(size_t)m * N + bn + col0] = o0;
        *(float4*)&C[(size_t)m * N + bn + col1] = o1;
    }
}

// ============================================================
// LayerNorm over H=512, in place. One CTA (256 thr) per row.
// ============================================================
__global__ void __launch_bounds__(256) ln_k(float* __restrict__ x,
                                            const float* __restrict__ g,
                                            const float* __restrict__ b)
{
    const int row = blockIdx.x;
    const int tid = threadIdx.x;
    float* xr = x + (size_t)row * HID;
    float v0 = xr[tid], v1 = xr[tid + 256];
    float s = v0 + v1;
#pragma unroll
    for (int o = 16; o; o >>= 1) s += __shfl_xor_sync(0xffffffffu, s, o);
    __shared__ float sm[8];
    const int w = tid >> 5, ln = tid & 31;
    if (ln == 0) sm[w] = s;
    __syncthreads();
    float mean = 0.f;
#pragma unroll
    for (int i = 0; i < 8; i++) mean += sm[i];
    mean *= (1.f / 512.f);
    const float d0 = v0 - mean, d1 = v1 - mean;
    float q = d0 * d0 + d1 * d1;
#pragma unroll
    for (int o = 16; o; o >>= 1) q += __shfl_xor_sync(0xffffffffu, q, o);
    __syncthreads();
    if (ln == 0) sm[w] = q;
    __syncthreads();
    float var = 0.f;
#pragma unroll
    for (int i = 0; i < 8; i++) var += sm[i];
    var *= (1.f / 512.f);
    const float r = rsqrtf(var + 1e-5f);
    xr[tid]       = d0 * r * g[tid] + b[tid];
    xr[tid + 256] = d1 * r * g[tid + 256] + b[tid + 256];
}

// ============================================================
// Pack [sem_w | epi_w] into g_wproj, biases into g_bproj.
// ============================================================
__global__ void pack_k(const float* __restrict__ sw, const float* __restrict__ ew,
                       const float* __restrict__ sb, const float* __restrict__ eb)
{
    const int idx = blockIdx.x * blockDim.x + threadIdx.x;   // 0..262143
    const int k = idx >> 9, n = idx & 511;
    g_wproj[idx] = (n < HALF_) ? sw[k * HALF_ + n] : ew[k * HALF_ + (n - HALF_)];
    if (idx < HID) g_bproj[idx] = (idx < HALF_) ? sb[idx] : eb[idx - HALF_];
}

// ============================================================
// inv_d = 1/(||k||^2 + 1e-6) for both halves; one warp per token.
// ============================================================
__global__ void __launch_bounds__(256) norms_k(const float* __restrict__ kall,
                                               float* __restrict__ invd)
{
    const int row = blockIdx.x * 8 + (threadIdx.x >> 5);
    const int ln = threadIdx.x & 31;
    const float* p = kall + (size_t)row * HID;
    float4 a0 = *(const float4*)(p + ln * 8);
    float4 a1 = *(const float4*)(p + ln * 8 + 4);
    float4 b0 = *(const float4*)(p + HALF_ + ln * 8);
    float4 b1 = *(const float4*)(p + HALF_ + ln * 8 + 4);
    float s0 = a0.x*a0.x + a0.y*a0.y + a0.z*a0.z + a0.w*a0.w
             + a1.x*a1.x + a1.y*a1.y + a1.z*a1.z + a1.w*a1.w;
    float s1 = b0.x*b0.x + b0.y*b0.y + b0.z*b0.z + b0.w*b0.w
             + b1.x*b1.x + b1.y*b1.y + b1.z*b1.z + b1.w*b1.w;
#pragma unroll
    for (int o = 16; o; o >>= 1) {
        s0 += __shfl_xor_sync(0xffffffffu, s0, o);
        s1 += __shfl_xor_sync(0xffffffffu, s1, o);
    }
    if (ln == 0) {
        invd[(size_t)row * 2 + 0] = 1.f / (s0 + 1e-6f);
        invd[(size_t)row * 2 + 1] = 1.f / (s1 + 1e-6f);
    }
}

// ============================================================
// Backward vector scan. 128 chains = (batch, {sem,epi}).
// u = q;  for t = T-1..0:  s = k_t . u;  c += w_t s k_t;  u -= w_t s invd_t k_t
// One warp per chain, 8 floats per lane.
// ============================================================
__global__ void __launch_bounds__(32) scan_k(const float* __restrict__ kall,
                                             const float* __restrict__ invd,
                                             float* __restrict__ cbuf)
{
    const int chain = blockIdx.x;       // 0..127
    const int b = chain >> 1, wh = chain & 1;
    const int ln = threadIdx.x;
    const float* base = kall + (size_t)b * SEQL * HID + wh * HALF_ + ln * 8;

    float u[8], acc[8];
    {
        float4 q0 = *(const float4*)(base + (size_t)(SEQL - 1) * HID);
        float4 q1 = *(const float4*)(base + (size_t)(SEQL - 1) * HID + 4);
        u[0]=q0.x; u[1]=q0.y; u[2]=q0.z; u[3]=q0.w;
        u[4]=q1.x; u[5]=q1.y; u[6]=q1.z; u[7]=q1.w;
    }
#pragma unroll
    for (int j = 0; j < 8; j++) acc[j] = 0.f;

    float kc[8];
    {
        float4 t0 = *(const float4*)(base + (size_t)(SEQL - 2) * HID);
        float4 t1 = *(const float4*)(base + (size_t)(SEQL - 2) * HID + 4);
        kc[0]=t0.x; kc[1]=t0.y; kc[2]=t0.z; kc[3]=t0.w;
        kc[4]=t1.x; kc[5]=t1.y; kc[6]=t1.z; kc[7]=t1.w;
    }

    for (int t = SEQL - 2; t >= 0; --t) {
        float kn[8] = {0,0,0,0,0,0,0,0};
        if (t > 0) {
            float4 t0 = *(const float4*)(base + (size_t)(t - 1) * HID);
            float4 t1 = *(const float4*)(base + (size_t)(t - 1) * HID + 4);
            kn[0]=t0.x; kn[1]=t0.y; kn[2]=t0.z; kn[3]=t0.w;
            kn[4]=t1.x; kn[5]=t1.y; kn[6]=t1.z; kn[7]=t1.w;
        }
        const float id = invd[((size_t)b * SEQL + t) * 2 + wh];
        // dot with pairwise tree to shorten the dependency chain
        float p0 = u[0]*kc[0] + u[1]*kc[1];
        float p1 = u[2]*kc[2] + u[3]*kc[3];
        float p2 = u[4]*kc[4] + u[5]*kc[5];
        float p3 = u[6]*kc[6] + u[7]*kc[7];
        float s = (p0 + p1) + (p2 + p3);
#pragma unroll
        for (int o = 16; o; o >>= 1) s += __shfl_xor_sync(0xffffffffu, s, o);
        const float w = wh ? (float)(t + 1) * (1.f / 1024.f) : 1.f;
        const float ws = w * s;
        const float us = ws * id;
#pragma unroll
        for (int j = 0; j < 8; j++) {
            acc[j] += ws * kc[j];
            u[j]   -= us * kc[j];
        }
#pragma unroll
        for (int j = 0; j < 8; j++) kc[j] = kn[j];
    }
    float4 o0 = make_float4(acc[0], acc[1], acc[2], acc[3]);
    float4 o1 = make_float4(acc[4], acc[5], acc[6], acc[7]);
    *(float4*)(cbuf + (size_t)b * HID + wh * HALF_ + ln * 8) = o0;
    *(float4*)(cbuf + (size_t)b * HID + wh * HALF_ + ln * 8 + 4) = o1;
}

// ============================================================
extern "C" void kernel_launch(void* const* d_in, const int* in_sizes, int n_in,
                              void* d_out, int out_size)
{
    const int*   seq   = (const int*)d_in[0];
    const float* embed = (const float*)d_in[1];
    const float* w1    = (const float*)d_in[2];
    const float* b1    = (const float*)d_in[3];
    const float* w2    = (const float*)d_in[4];
    const float* b2    = (const float*)d_in[5];
    const float* lng   = (const float*)d_in[6];
    const float* lnb   = (const float*)d_in[7];
    const float* sw    = (const float*)d_in[8];
    const float* sb    = (const float*)d_in[9];
    const float* ew    = (const float*)d_in[10];
    const float* eb    = (const float*)d_in[11];
    const float* ow    = (const float*)d_in[12];
    const float* ob    = (const float*)d_in[13];
    float* out = (float*)d_out;

    static float *buf1 = nullptr, *xb = nullptr, *kb = nullptr, *wp = nullptr,
                 *bp = nullptr, *ivd = nullptr, *cb = nullptr;
    if (!buf1) {
        cudaGetSymbolAddress((void**)&buf1, g_buf1);
        cudaGetSymbolAddress((void**)&xb,   g_x);
        cudaGetSymbolAddress((void**)&kb,   g_k);
        cudaGetSymbolAddress((void**)&wp,   g_wproj);
        cudaGetSymbolAddress((void**)&bp,   g_bproj);
        cudaGetSymbolAddress((void**)&ivd,  g_invd);
        cudaGetSymbolAddress((void**)&cb,   g_c);
    }

    // pack projection weights (independent of GEMM1/2; same stream ordering is fine)
    pack_k<<<512, 512>>>(sw, ew, sb, eb);

    // GEMM1: buf1 = relu(embed[seq] @ w1 + b1)   [65536 x 1024, K=512]
    sgemm_k<true, 0><<<dim3(FF / 128, TOK / 128), 256>>>(
        TOK, FF, HID, nullptr, w1, b1, buf1, seq, embed);

    // GEMM2: x = buf1 @ w2 + b2 + embed[seq]     [65536 x 512, K=1024]
    sgemm_k<false, 1><<<dim3(HID / 128, TOK / 128), 256>>>(
        TOK, HID, FF, buf1, w2, b2, xb, seq, embed);

    // LayerNorm in place: x -> h
    ln_k<<<TOK, 256>>>(xb, lng, lnb);

    // GEMM3: k = h @ [sem_w|epi_w] + [sem_b|epi_b]   [65536 x 512, K=512]
    sgemm_k<false, 2><<<dim3(HID / 128, TOK / 128), 256>>>(
        TOK, HID, HID, xb, wp, bp, kb, nullptr, nullptr);

    // per-token inverse squared norms
    norms_k<<<TOK / 8, 256>>>(kb, ivd);

    // backward vector scan -> c = [cs | ce]  (64 x 512)
    scan_k<<<128, 32>>>(kb, ivd, cb);

    // GEMM4: out = c @ out_w + out_b   [64 x 32000, K=512]
    sgemm_k<false, 2><<<dim3(VOC / 128, 1), 256>>>(
        BATCH, VOC, HID, cb, ow, ob, out, nullptr, nullptr);
}

// round 2
// speedup vs baseline: 1.0213x; 1.0213x over previous
#include <cuda_runtime.h>
#include <cuda_bf16.h>
#include <cstdint>

// Problem constants
#define TOK   65536      // B*L
#define BATCH 64
#define SEQL  1024
#define HID   512
#define FF    1024
#define HALF_ 256
#define VOC   32000

// -------- scratch (device globals; no allocation allowed) --------
__device__ float g_buf1[(size_t)TOK * FF];    // relu(e@W1+b1)
__device__ float g_x[(size_t)TOK * HID];      // x -> h (LN in place)
__device__ float g_k[(size_t)TOK * HID];      // [ks | ke] per token
__device__ float g_wproj[HID * HID];          // [sem_w | epi_w]
__device__ float g_bproj[HID];
__device__ float g_invd[(size_t)TOK * 2];     // 1/(||k||^2+eps) per (token, {s,e})
__device__ float g_c[BATCH * HID];            // [cs | ce]

// ---- packed f32x2 helpers (Blackwell FFMA2 path; PTX-only, ptxas won't emit) ----
__device__ __forceinline__ unsigned long long pk2(float x, float y) {
    unsigned long long r;
    asm("mov.b64 %0, {%1, %2};" : "=l"(r) : "f"(x), "f"(y));
    return r;
}
__device__ __forceinline__ void ffma2(unsigned long long& d,
                                      unsigned long long a, unsigned long long b) {
    asm("fma.rn.f32x2 %0, %1, %2, %0;" : "+l"(d) : "l"(a), "l"(b));
}
__device__ __forceinline__ float2 upk2(unsigned long long v) {
    float2 p;
    asm("mov.b64 {%0, %1}, %2;" : "=f"(p.x), "=f"(p.y) : "l"(v));
    return p;
}

// ============================================================
// Tiled SGEMM with FFMA2 inner loop.
// C[M,N] = op(A)[M,K] @ B[K,N] + bias, epilogues.
// BM=BN=128, BK=16, 256 threads, 8x8 outputs per thread
// (rows paired into f32x2 accumulators: 4x8 packed accs).
// GATHER_A: A row m is embed[seq[m]] (K must equal HID).
// EPI: 0 = relu(acc+bias); 1 = acc+bias+embed[seq[m]][n] (N==HID); 2 = acc+bias
// Requirements: N % 128 == 0, K % 16 == 0. M arbitrary (guarded).
// ============================================================
template<bool GATHER_A, int EPI>
__global__ void __launch_bounds__(256) sgemm_k(
    int M, int N, int K,
    const float* __restrict__ A, const float* __restrict__ Bm,
    const float* __restrict__ bias, float* __restrict__ C,
    const int* __restrict__ seq, const float* __restrict__ embed)
{
    __shared__ float As[16][128];
    __shared__ float Bs[16][128];
    const int tid = threadIdx.x;
    const int bm = blockIdx.y * 128;
    const int bn = blockIdx.x * 128;
    const int tx = tid & 15;        // 0..15
    const int ty = tid >> 4;        // 0..15
    const int row0 = ty * 4, row1 = ty * 4 + 64;
    const int col0 = tx * 4, col1 = tx * 4 + 64;

    // packed accumulators: acc2[ip][j]
    //   ip=0 -> rows (row0, row0+1), ip=1 -> (row0+2, row0+3)
    //   ip=2 -> rows (row1, row1+1), ip=3 -> (row1+2, row1+3)
    unsigned long long acc2[4][8];
#pragma unroll
    for (int i = 0; i < 4; i++)
#pragma unroll
        for (int j = 0; j < 8; j++) acc2[i][j] = 0ull;

    const int a_r0 = tid >> 2;          // 0..63
    const int a_c  = (tid & 3) * 4;     // 0,4,8,12
    const int b_r0 = tid >> 5;          // 0..7
    const int b_c  = (tid & 31) * 4;    // 0..124

    for (int k0 = 0; k0 < K; k0 += 16) {
        // ---- load A tile (transposed into As[k][m]) ----
#pragma unroll
        for (int i = 0; i < 2; i++) {
            const int mr = a_r0 + i * 64;
            const int m = bm + mr;
            float4 v = make_float4(0.f, 0.f, 0.f, 0.f);
            if (m < M) {
                const float* ap;
                if (GATHER_A) ap = embed + (size_t)seq[m] * K + (k0 + a_c);
                else          ap = A + (size_t)m * K + (k0 + a_c);
                v = *(const float4*)ap;
            }
            As[a_c + 0][mr] = v.x;
            As[a_c + 1][mr] = v.y;
            As[a_c + 2][mr] = v.z;
            As[a_c + 3][mr] = v.w;
        }
        // ---- load B tile ----
#pragma unroll
        for (int i = 0; i < 2; i++) {
            const int kr = k0 + b_r0 + i * 8;
            float4 v = *(const float4*)(Bm + (size_t)kr * N + bn + b_c);
            *(float4*)&Bs[b_r0 + i * 8][b_c] = v;
        }
        __syncthreads();
        // ---- compute (FFMA2) ----
#pragma unroll
        for (int kk = 0; kk < 16; kk++) {
            // A row pairs: 16B aligned (row0, row1 are multiples of 4)
            ulonglong2 a01 = *(const ulonglong2*)&As[kk][row0];
            ulonglong2 a23 = *(const ulonglong2*)&As[kk][row1];
            float4 rb0 = *(const float4*)&Bs[kk][col0];
            float4 rb1 = *(const float4*)&Bs[kk][col1];
            unsigned long long pa[4] = {a01.x, a01.y, a23.x, a23.y};
            unsigned long long bd[8];
            bd[0] = pk2(rb0.x, rb0.x); bd[1] = pk2(rb0.y, rb0.y);
            bd[2] = pk2(rb0.z, rb0.z); bd[3] = pk2(rb0.w, rb0.w);
            bd[4] = pk2(rb1.x, rb1.x); bd[5] = pk2(rb1.y, rb1.y);
            bd[6] = pk2(rb1.z, rb1.z); bd[7] = pk2(rb1.w, rb1.w);
#pragma unroll
            for (int ip = 0; ip < 4; ip++)
#pragma unroll
                for (int j = 0; j < 8; j++)
                    ffma2(acc2[ip][j], pa[ip], bd[j]);
        }
        __syncthreads();
    }

    // ---- unpack accumulators to acc[i][j] (i: 0..3 -> row0+i, 4..7 -> row1+(i-4)) ----
    float acc[8][8];
#pragma unroll
    for (int ip = 0; ip < 4; ip++) {
        const int ibase = (ip < 2) ? (ip * 2) : (4 + (ip - 2) * 2);
#pragma unroll
        for (int j = 0; j < 8; j++) {
            float2 p = upk2(acc2[ip][j]);
            acc[ibase + 0][j] = p.x;
            acc[ibase + 1][j] = p.y;
        }
    }

    // ---- epilogue ----
    float4 bi0 = *(const float4*)&bias[bn + col0];
    float4 bi1 = *(const float4*)&bias[bn + col1];
    const float bb0[4] = {bi0.x, bi0.y, bi0.z, bi0.w};
    const float bb1[4] = {bi1.x, bi1.y, bi1.z, bi1.w};
#pragma unroll
    for (int i = 0; i < 8; i++) {
        const int m = bm + ((i < 4) ? (row0 + i) : (row1 + i - 4));
        if (m >= M) continue;
        float v0[4], v1[4];
#pragma unroll
        for (int j = 0; j < 4; j++) { v0[j] = acc[i][j] + bb0[j]; v1[j] = acc[i][j + 4] + bb1[j]; }
        if (EPI == 0) {
#pragma unroll
            for (int j = 0; j < 4; j++) { v0[j] = fmaxf(v0[j], 0.f); v1[j] = fmaxf(v1[j], 0.f); }
        }
        if (EPI == 1) {
            const size_t er = (size_t)seq[m] * N;   // N == HID here
            float4 e0 = *(const float4*)&embed[er + bn + col0];
            float4 e1 = *(const float4*)&embed[er + bn + col1];
            v0[0] += e0.x; v0[1] += e0.y; v0[2] += e0.z; v0[3] += e0.w;
            v1[0] += e1.x; v1[1] += e1.y; v1[2] += e1.z; v1[3] += e1.w;
        }
        float4 o0 = make_float4(v0[0], v0[1], v0[2], v0[3]);
        float4 o1 = make_float4(v1[0], v1[1], v1[2], v1[3]);
        *(float4*)&C[(size_t)m * N + bn + col0] = o0;
        *(float4*)&C[(size_t)m * N + bn + col1] = o1;
    }
}

// ============================================================
// LayerNorm over H=512, in place. One CTA (256 thr) per row.
// ============================================================
__global__ void __launch_bounds__(256) ln_k(float* __restrict__ x,
                                            const float* __restrict__ g,
                                            const float* __restrict__ b)
{
    const int row = blockIdx.x;
    const int tid = threadIdx.x;
    float* xr = x + (size_t)row * HID;
    float v0 = xr[tid], v1 = xr[tid + 256];
    float s = v0 + v1;
#pragma unroll
    for (int o = 16; o; o >>= 1) s += __shfl_xor_sync(0xffffffffu, s, o);
    __shared__ float sm[8];
    const int w = tid >> 5, ln = tid & 31;
    if (ln == 0) sm[w] = s;
    __syncthreads();
    float mean = 0.f;
#pragma unroll
    for (int i = 0; i < 8; i++) mean += sm[i];
    mean *= (1.f / 512.f);
    const float d0 = v0 - mean, d1 = v1 - mean;
    float q = d0 * d0 + d1 * d1;
#pragma unroll
    for (int o = 16; o; o >>= 1) q += __shfl_xor_sync(0xffffffffu, q, o);
    __syncthreads();
    if (ln == 0) sm[w] = q;
    __syncthreads();
    float var = 0.f;
#pragma unroll
    for (int i = 0; i < 8; i++) var += sm[i];
    var *= (1.f / 512.f);
    const float r = rsqrtf(var + 1e-5f);
    xr[tid]       = d0 * r * g[tid] + b[tid];
    xr[tid + 256] = d1 * r * g[tid + 256] + b[tid + 256];
}

// ============================================================
// Pack [sem_w | epi_w] into g_wproj, biases into g_bproj.
// ============================================================
__global__ void pack_k(const float* __restrict__ sw, const float* __restrict__ ew,
                       const float* __restrict__ sb, const float* __restrict__ eb)
{
    const int idx = blockIdx.x * blockDim.x + threadIdx.x;   // 0..262143
    const int k = idx >> 9, n = idx & 511;
    g_wproj[idx] = (n < HALF_) ? sw[k * HALF_ + n] : ew[k * HALF_ + (n - HALF_)];
    if (idx < HID) g_bproj[idx] = (idx < HALF_) ? sb[idx] : eb[idx - HALF_];
}

// ============================================================
// inv_d = 1/(||k||^2 + 1e-6) for both halves; one warp per token.
// ============================================================
__global__ void __launch_bounds__(256) norms_k(const float* __restrict__ kall,
                                               float* __restrict__ invd)
{
    const int row = blockIdx.x * 8 + (threadIdx.x >> 5);
    const int ln = threadIdx.x & 31;
    const float* p = kall + (size_t)row * HID;
    float4 a0 = *(const float4*)(p + ln * 8);
    float4 a1 = *(const float4*)(p + ln * 8 + 4);
    float4 b0 = *(const float4*)(p + HALF_ + ln * 8);
    float4 b1 = *(const float4*)(p + HALF_ + ln * 8 + 4);
    float s0 = a0.x*a0.x + a0.y*a0.y + a0.z*a0.z + a0.w*a0.w
             + a1.x*a1.x + a1.y*a1.y + a1.z*a1.z + a1.w*a1.w;
    float s1 = b0.x*b0.x + b0.y*b0.y + b0.z*b0.z + b0.w*b0.w
             + b1.x*b1.x + b1.y*b1.y + b1.z*b1.z + b1.w*b1.w;
#pragma unroll
    for (int o = 16; o; o >>= 1) {
        s0 += __shfl_xor_sync(0xffffffffu, s0, o);
        s1 += __shfl_xor_sync(0xffffffffu, s1, o);
    }
    if (ln == 0) {
        invd[(size_t)row * 2 + 0] = 1.f / (s0 + 1e-6f);
        invd[(size_t)row * 2 + 1] = 1.f / (s1 + 1e-6f);
    }
}

// ============================================================
// Backward vector scan. 128 chains = (batch, {sem,epi}).
// u = q;  for t = T-1..0:  s = k_t . u;  c += w_t s k_t;  u -= w_t s invd_t k_t
// One warp per chain, 8 floats per lane.
// ============================================================
__global__ void __launch_bounds__(32) scan_k(const float* __restrict__ kall,
                                             const float* __restrict__ invd,
                                             float* __restrict__ cbuf)
{
    const int chain = blockIdx.x;       // 0..127
    const int b = chain >> 1, wh = chain & 1;
    const int ln = threadIdx.x;
    const float* base = kall + (size_t)b * SEQL * HID + wh * HALF_ + ln * 8;

    float u[8], acc[8];
    {
        float4 q0 = *(const float4*)(base + (size_t)(SEQL - 1) * HID);
        float4 q1 = *(const float4*)(base + (size_t)(SEQL - 1) * HID + 4);
        u[0]=q0.x; u[1]=q0.y; u[2]=q0.z; u[3]=q0.w;
        u[4]=q1.x; u[5]=q1.y; u[6]=q1.z; u[7]=q1.w;
    }
#pragma unroll
    for (int j = 0; j < 8; j++) acc[j] = 0.f;

    float kc[8];
    {
        float4 t0 = *(const float4*)(base + (size_t)(SEQL - 2) * HID);
        float4 t1 = *(const float4*)(base + (size_t)(SEQL - 2) * HID + 4);
        kc[0]=t0.x; kc[1]=t0.y; kc[2]=t0.z; kc[3]=t0.w;
        kc[4]=t1.x; kc[5]=t1.y; kc[6]=t1.z; kc[7]=t1.w;
    }

    for (int t = SEQL - 2; t >= 0; --t) {
        float kn[8] = {0,0,0,0,0,0,0,0};
        if (t > 0) {
            float4 t0 = *(const float4*)(base + (size_t)(t - 1) * HID);
            float4 t1 = *(const float4*)(base + (size_t)(t - 1) * HID + 4);
            kn[0]=t0.x; kn[1]=t0.y; kn[2]=t0.z; kn[3]=t0.w;
            kn[4]=t1.x; kn[5]=t1.y; kn[6]=t1.z; kn[7]=t1.w;
        }
        const float id = invd[((size_t)b * SEQL + t) * 2 + wh];
        // dot with pairwise tree to shorten the dependency chain
        float p0 = u[0]*kc[0] + u[1]*kc[1];
        float p1 = u[2]*kc[2] + u[3]*kc[3];
        float p2 = u[4]*kc[4] + u[5]*kc[5];
        float p3 = u[6]*kc[6] + u[7]*kc[7];
        float s = (p0 + p1) + (p2 + p3);
#pragma unroll
        for (int o = 16; o; o >>= 1) s += __shfl_xor_sync(0xffffffffu, s, o);
        const float w = wh ? (float)(t + 1) * (1.f / 1024.f) : 1.f;
        const float ws = w * s;
        const float us = ws * id;
#pragma unroll
        for (int j = 0; j < 8; j++) {
            acc[j] += ws * kc[j];
            u[j]   -= us * kc[j];
        }
#pragma unroll
        for (int j = 0; j < 8; j++) kc[j] = kn[j];
    }
    float4 o0 = make_float4(acc[0], acc[1], acc[2], acc[3]);
    float4 o1 = make_float4(acc[4], acc[5], acc[6], acc[7]);
    *(float4*)(cbuf + (size_t)b * HID + wh * HALF_ + ln * 8) = o0;
    *(float4*)(cbuf + (size_t)b * HID + wh * HALF_ + ln * 8 + 4) = o1;
}

// ============================================================
extern "C" void kernel_launch(void* const* d_in, const int* in_sizes, int n_in,
                              void* d_out, int out_size)
{
    const int*   seq   = (const int*)d_in[0];
    const float* embed = (const float*)d_in[1];
    const float* w1    = (const float*)d_in[2];
    const float* b1    = (const float*)d_in[3];
    const float* w2    = (const float*)d_in[4];
    const float* b2    = (const float*)d_in[5];
    const float* lng   = (const float*)d_in[6];
    const float* lnb   = (const float*)d_in[7];
    const float* sw    = (const float*)d_in[8];
    const float* sb    = (const float*)d_in[9];
    const float* ew    = (const float*)d_in[10];
    const float* eb    = (const float*)d_in[11];
    const float* ow    = (const float*)d_in[12];
    const float* ob    = (const float*)d_in[13];
    float* out = (float*)d_out;

    static float *buf1 = nullptr, *xb = nullptr, *kb = nullptr, *wp = nullptr,
                 *bp = nullptr, *ivd = nullptr, *cb = nullptr;
    if (!buf1) {
        cudaGetSymbolAddress((void**)&buf1, g_buf1);
        cudaGetSymbolAddress((void**)&xb,   g_x);
        cudaGetSymbolAddress((void**)&kb,   g_k);
        cudaGetSymbolAddress((void**)&wp,   g_wproj);
        cudaGetSymbolAddress((void**)&bp,   g_bproj);
        cudaGetSymbolAddress((void**)&ivd,  g_invd);
        cudaGetSymbolAddress((void**)&cb,   g_c);
    }

    // pack projection weights (independent of GEMM1/2; same stream ordering is fine)
    pack_k<<<512, 512>>>(sw, ew, sb, eb);

    // GEMM1: buf1 = relu(embed[seq] @ w1 + b1)   [65536 x 1024, K=512]
    sgemm_k<true, 0><<<dim3(FF / 128, TOK / 128), 256>>>(
        TOK, FF, HID, nullptr, w1, b1, buf1, seq, embed);

    // GEMM2: x = buf1 @ w2 + b2 + embed[seq]     [65536 x 512, K=1024]
    sgemm_k<false, 1><<<dim3(HID / 128, TOK / 128), 256>>>(
        TOK, HID, FF, buf1, w2, b2, xb, seq, embed);

    // LayerNorm in place: x -> h
    ln_k<<<TOK, 256>>>(xb, lng, lnb);

    // GEMM3: k = h @ [sem_w|epi_w] + [sem_b|epi_b]   [65536 x 512, K=512]
    sgemm_k<false, 2><<<dim3(HID / 128, TOK / 128), 256>>>(
        TOK, HID, HID, xb, wp, bp, kb, nullptr, nullptr);

    // per-token inverse squared norms
    norms_k<<<TOK / 8, 256>>>(kb, ivd);

    // backward vector scan -> c = [cs | ce]  (64 x 512)
    scan_k<<<128, 32>>>(kb, ivd, cb);

    // GEMM4: out = c @ out_w + out_b   [64 x 32000, K=512]
    sgemm_k<false, 2><<<dim3(VOC / 128, 1), 256>>>(
        BATCH, VOC, HID, cb, ow, ob, out, nullptr, nullptr);
}

// round 4
// speedup vs baseline: 2.3123x; 2.2641x over previous
#include <cuda_runtime.h>
#include <cuda_bf16.h>
#include <cstdint>

// Problem constants
#define TOK   65536      // B*L
#define BATCH 64
#define SEQL  1024
#define HID   512
#define FF    1024
#define HALF_ 256
#define VOC   32000

typedef __nv_bfloat16 bf16;

__device__ __forceinline__ uint32_t smem_u32(const void* p) {
    uint32_t a;
    asm("{ .reg .u64 t; cvta.to.shared.u64 t, %1; cvt.u32.u64 %0, t; }" : "=r"(a) : "l"(p));
    return a;
}
#define SW128(o) ((o) ^ (((o) >> 3) & 0x70))

__device__ __forceinline__ void ldsm4(uint32_t* r, uint32_t a) {
    asm volatile("ldmatrix.sync.aligned.m8n8.x4.shared.b16 {%0,%1,%2,%3}, [%4];"
        : "=r"(r[0]), "=r"(r[1]), "=r"(r[2]), "=r"(r[3]) : "r"(a));
}
__device__ __forceinline__ void ldsm2(uint32_t* r, uint32_t a) {
    asm volatile("ldmatrix.sync.aligned.m8n8.x2.shared.b16 {%0,%1}, [%2];"
        : "=r"(r[0]), "=r"(r[1]) : "r"(a));
}
__device__ __forceinline__ void mma16816(float* c, const uint32_t* a, const uint32_t* b) {
    asm volatile("mma.sync.aligned.m16n8k16.row.col.f32.bf16.bf16.f32 "
        "{%0,%1,%2,%3}, {%4,%5,%6,%7}, {%8,%9}, {%0,%1,%2,%3};"
        : "+f"(c[0]), "+f"(c[1]), "+f"(c[2]), "+f"(c[3])
        : "r"(a[0]), "r"(a[1]), "r"(a[2]), "r"(a[3]), "r"(b[0]), "r"(b[1]));
}

__device__ __forceinline__ void split2(float x, bf16& h, bf16& l) {
    h = __float2bfloat16(x);
    l = __float2bfloat16(x - __bfloat162float(h));
}

// -------- scratch (device globals) --------
__device__ bf16  g_ah[(size_t)TOK * HID],  g_al[(size_t)TOK * HID];
__device__ bf16  g_h1h[(size_t)TOK * FF],  g_h1l[(size_t)TOK * FF];
__device__ bf16  g_hh[(size_t)TOK * HID],  g_hl[(size_t)TOK * HID];
__device__ float g_x[(size_t)TOK * HID];
__device__ float g_k[(size_t)TOK * HID];
__device__ bf16  g_w1h[(size_t)FF * HID],  g_w1l[(size_t)FF * HID];
__device__ bf16  g_w2h[(size_t)HID * FF],  g_w2l[(size_t)HID * FF];
__device__ bf16  g_wph[(size_t)HID * HID], g_wpl[(size_t)HID * HID];
__device__ bf16  g_owh[(size_t)VOC * HID], g_owl[(size_t)VOC * HID];
__device__ float g_bproj[HID];
__device__ float g_invd[(size_t)TOK * 2];
__device__ float g_c[BATCH * HID];
__device__ bf16  g_ch[BATCH * HID], g_cl[BATCH * HID];

// ============================================================
// mma.sync split-bf16 GEMM.  C[M,N] = A[M,K] @ B^T
//   A given [M,K] K-major as hi/lo bf16; B given [N,K] K-major hi/lo.
//   C = Ah*Bh + Ah*Bl + Al*Bh  (3-pass split, ~16 mantissa bits)
// 128x128 CTA tile, BK=32, 256 threads (8 warps, each 64x32),
// smem rows pack [hi 64B | lo 64B], SW128 swizzle, single buffer.
// EPI: 0 = relu(acc+bias) -> split bf16 (Chi/Clo)
//      1 = acc+bias+embed[seq[m]] -> fp32 Cf   (N==HID)
//      2 = acc+bias -> fp32 Cf
// N % 128 == 0, K % 32 == 0; M guarded.
// ============================================================
template<int EPI>
__global__ void __launch_bounds__(256, 2) mma_gemm(
    int Mrows, int N, int K,
    const bf16* __restrict__ Ah, const bf16* __restrict__ Al,
    const bf16* __restrict__ Bh, const bf16* __restrict__ Bl,
    const float* __restrict__ bias,
    float* __restrict__ Cf, bf16* __restrict__ Chi, bf16* __restrict__ Clo,
    const int* __restrict__ seq, const float* __restrict__ embed)
{
    __shared__ __align__(1024) char sA[16384];   // 128 rows x [hi 64B | lo 64B]
    __shared__ __align__(1024) char sB[16384];
    const uint32_t sAu = smem_u32(sA);
    const uint32_t sBu = smem_u32(sB);
    const int tid = threadIdx.x;
    const int bm = blockIdx.y * 128;
    const int bn = blockIdx.x * 128;
    const int wid = tid >> 5, lane = tid & 31;
    const int wm = (wid >> 2) * 64;     // warp row offset (0 / 64)
    const int wn = (wid & 3) * 32;      // warp col offset (0..96)
    const bool mguard = (Mrows & 127) != 0;

    // loader mapping: 2 threads per row, each 2x16B per half
    const int lrow = tid >> 1;
    const int lw = (tid & 1) * 2;       // word pair {lw, lw+1}, word=16B

    // ldmatrix lane addressing
    const int a_mi = lane >> 3;
    const int a_row = (lane & 7) + (a_mi & 1) * 8;   // row within m16 tile
    const int a_kb = (a_mi >> 1) * 16;               // byte offset within k16
    const int b_row = lane & 7;                      // row within n8 tile
    const int b_kb = ((lane >> 3) & 1) * 16;

    float c[16][4];
#pragma unroll
    for (int i = 0; i < 16; i++)
#pragma unroll
        for (int j = 0; j < 4; j++) c[i][j] = 0.f;

    for (int k0 = 0; k0 < K; k0 += 32) {
        // ---- load stage ----
#pragma unroll
        for (int it = 0; it < 2; it++) {
            const int word = lw + it;                // 0..3 (16B units of 64B half-row)
            const uint32_t soh = SW128((uint32_t)(lrow * 128 + word * 16));
            const uint32_t sol = SW128((uint32_t)(lrow * 128 + 64 + word * 16));
            // A
            {
                const int m = bm + lrow;
                uint4 vh = make_uint4(0, 0, 0, 0), vl = make_uint4(0, 0, 0, 0);
                if (!mguard || m < Mrows) {
                    const size_t off = (size_t)m * K + k0 + word * 8;
                    vh = *(const uint4*)(Ah + off);
                    vl = *(const uint4*)(Al + off);
                }
                *(uint4*)(sA + soh) = vh;
                *(uint4*)(sA + sol) = vl;
            }
            // B
            {
                const size_t off = (size_t)(bn + lrow) * K + k0 + word * 8;
                *(uint4*)(sB + soh) = *(const uint4*)(Bh + off);
                *(uint4*)(sB + sol) = *(const uint4*)(Bl + off);
            }
        }
        __syncthreads();
        // ---- compute: 2 k16 steps, 3 passes each ----
#pragma unroll
        for (int k16 = 0; k16 < 2; k16++) {
            const int kb = k16 * 32;
            uint32_t bh[4][2], bl[4][2];
#pragma unroll
            for (int nt = 0; nt < 4; nt++) {
                const uint32_t rb = (uint32_t)((wn + nt * 8 + b_row) * 128);
                ldsm2(bh[nt], sBu + SW128(rb + kb + b_kb));
                ldsm2(bl[nt], sBu + SW128(rb + 64 + kb + b_kb));
            }
            uint32_t a[4][4];
#pragma unroll
            for (int mt = 0; mt < 4; mt++)
                ldsm4(a[mt], sAu + SW128((uint32_t)((wm + mt * 16 + a_row) * 128) + kb + a_kb));
#pragma unroll
            for (int mt = 0; mt < 4; mt++)
#pragma unroll
                for (int nt = 0; nt < 4; nt++) {
                    mma16816(c[mt * 4 + nt], a[mt], bh[nt]);
                    mma16816(c[mt * 4 + nt], a[mt], bl[nt]);
                }
            // lo(A) x hi(B)
#pragma unroll
            for (int mt = 0; mt < 4; mt++)
                ldsm4(a[mt], sAu + SW128((uint32_t)((wm + mt * 16 + a_row) * 128) + 64 + kb + a_kb));
#pragma unroll
            for (int mt = 0; mt < 4; mt++)
#pragma unroll
                for (int nt = 0; nt < 4; nt++)
                    mma16816(c[mt * 4 + nt], a[mt], bh[nt]);
        }
        __syncthreads();
    }

    // ---- epilogue ----
    const int mrow = lane >> 2;          // 0..7
    const int mcol = (lane & 3) * 2;
#pragma unroll
    for (int mt = 0; mt < 4; mt++) {
        const int r0 = bm + wm + mt * 16 + mrow;
        const int r1 = r0 + 8;
        const bool v0 = !mguard || (r0 < Mrows);
        const bool v1 = !mguard || (r1 < Mrows);
        const float* e0 = nullptr;
        const float* e1 = nullptr;
        if (EPI == 1) {
            if (v0) e0 = embed + (size_t)seq[r0] * HID;
            if (v1) e1 = embed + (size_t)seq[r1] * HID;
        }
#pragma unroll
        for (int nt = 0; nt < 4; nt++) {
            const int col = bn + wn + nt * 8 + mcol;
            float* cc = c[mt * 4 + nt];
            const float b0v = bias[col], b1v = bias[col + 1];
            float x0 = cc[0] + b0v, x1 = cc[1] + b1v;
            float x2 = cc[2] + b0v, x3 = cc[3] + b1v;
            if (EPI == 0) {
                x0 = fmaxf(x0, 0.f); x1 = fmaxf(x1, 0.f);
                x2 = fmaxf(x2, 0.f); x3 = fmaxf(x3, 0.f);
                bf16 h0, l0, h1, l1;
                if (v0) {
                    split2(x0, h0, l0); split2(x1, h1, l1);
                    __nv_bfloat162 ph; ph.x = h0; ph.y = h1;
                    __nv_bfloat162 pl; pl.x = l0; pl.y = l1;
                    *(__nv_bfloat162*)(Chi + (size_t)r0 * N + col) = ph;
                    *(__nv_bfloat162*)(Clo + (size_t)r0 * N + col) = pl;
                }
                if (v1) {
                    split2(x2, h0, l0); split2(x3, h1, l1);
                    __nv_bfloat162 ph; ph.x = h0; ph.y = h1;
                    __nv_bfloat162 pl; pl.x = l0; pl.y = l1;
                    *(__nv_bfloat162*)(Chi + (size_t)r1 * N + col) = ph;
                    *(__nv_bfloat162*)(Clo + (size_t)r1 * N + col) = pl;
                }
            } else {
                if (EPI == 1) {
                    if (v0) { x0 += e0[col]; x1 += e0[col + 1]; }
                    if (v1) { x2 += e1[col]; x3 += e1[col + 1]; }
                }
                if (v0) *(float2*)(Cf + (size_t)r0 * N + col) = make_float2(x0, x1);
                if (v1) *(float2*)(Cf + (size_t)r1 * N + col) = make_float2(x2, x3);
            }
        }
    }
}

// ============================================================
// gather + split:  Ahi/Alo[m] = split(embed[seq[m]])
// ============================================================
__global__ void __launch_bounds__(256) gsplit_k(const int* __restrict__ seq,
                                                const float* __restrict__ embed,
                                                bf16* __restrict__ hi, bf16* __restrict__ lo)
{
    const size_t idx = (size_t)blockIdx.x * 256 + threadIdx.x;   // TOK*64
    const int t = (int)(idx >> 6), c = (int)(idx & 63) * 8;
    const float* p = embed + (size_t)seq[t] * HID + c;
    float4 a = *(const float4*)p;
    float4 b = *(const float4*)(p + 4);
    float vv[8] = {a.x, a.y, a.z, a.w, b.x, b.y, b.z, b.w};
    const size_t ob = (size_t)t * HID + c;
#pragma unroll
    for (int j = 0; j < 8; j += 2) {
        bf16 h0, l0, h1, l1;
        split2(vv[j], h0, l0);
        split2(vv[j + 1], h1, l1);
        __nv_bfloat162 ph; ph.x = h0; ph.y = h1;
        __nv_bfloat162 pl; pl.x = l0; pl.y = l1;
        *(__nv_bfloat162*)(hi + ob + j) = ph;
        *(__nv_bfloat162*)(lo + ob + j) = pl;
    }
}

// ============================================================
// Tiled transpose + split: W[K,N] fp32 -> out[N,K] hi/lo bf16.
// ============================================================
__global__ void __launch_bounds__(256) tsplit_k(const float* __restrict__ W, int K, int N,
                                                bf16* __restrict__ ht, bf16* __restrict__ lt)
{
    __shared__ float t[32][33];
    const int tx = threadIdx.x & 31, ty = threadIdx.x >> 5;
    const int n0 = blockIdx.x * 32, k0 = blockIdx.y * 32;
#pragma unroll
    for (int i = 0; i < 4; i++)
        t[ty + 8 * i][tx] = W[(size_t)(k0 + ty + 8 * i) * N + n0 + tx];
    __syncthreads();
#pragma unroll
    for (int i = 0; i < 4; i++) {
        float v = t[tx][ty + 8 * i];
        bf16 h, l;
        split2(v, h, l);
        const size_t o = (size_t)(n0 + ty + 8 * i) * K + k0 + tx;
        ht[o] = h;
        lt[o] = l;
    }
}

// ============================================================
// LayerNorm (warp per row) + split output to bf16 hi/lo.
// ============================================================
__global__ void __launch_bounds__(256) ln_split_k(const float* __restrict__ x,
                                                  const float* __restrict__ g,
                                                  const float* __restrict__ b,
                                                  bf16* __restrict__ hh, bf16* __restrict__ hl)
{
    const int row = blockIdx.x * 8 + (threadIdx.x >> 5);
    const int ln = threadIdx.x & 31;
    const float* xr = x + (size_t)row * HID + ln * 16;
    float v[16];
    *(float4*)&v[0]  = ((const float4*)xr)[0];
    *(float4*)&v[4]  = ((const float4*)xr)[1];
    *(float4*)&v[8]  = ((const float4*)xr)[2];
    *(float4*)&v[12] = ((const float4*)xr)[3];
    float s = 0.f;
#pragma unroll
    for (int j = 0; j < 16; j++) s += v[j];
#pragma unroll
    for (int o = 16; o; o >>= 1) s += __shfl_xor_sync(0xffffffffu, s, o);
    const float mean = s * (1.f / 512.f);
    float q = 0.f;
#pragma unroll
    for (int j = 0; j < 16; j++) { float d = v[j] - mean; q += d * d; }
#pragma unroll
    for (int o = 16; o; o >>= 1) q += __shfl_xor_sync(0xffffffffu, q, o);
    const float r = rsqrtf(q * (1.f / 512.f) + 1e-5f);
    const size_t ob = (size_t)row * HID + ln * 16;
#pragma unroll
    for (int j = 0; j < 16; j += 2) {
        const int c0 = ln * 16 + j;
        float y0 = (v[j] - mean) * r * g[c0] + b[c0];
        float y1 = (v[j + 1] - mean) * r * g[c0 + 1] + b[c0 + 1];
        bf16 h0, l0, h1, l1;
        split2(y0, h0, l0);
        split2(y1, h1, l1);
        __nv_bfloat162 ph; ph.x = h0; ph.y = h1;
        __nv_bfloat162 pl; pl.x = l0; pl.y = l1;
        *(__nv_bfloat162*)(hh + ob + j) = ph;
        *(__nv_bfloat162*)(hl + ob + j) = pl;
    }
}

// ============================================================
__global__ void bpack_k(const float* __restrict__ sb, const float* __restrict__ eb)
{
    const int i = blockIdx.x * 256 + threadIdx.x;
    if (i < HID) g_bproj[i] = (i < HALF_) ? sb[i] : eb[i - HALF_];
}

__global__ void __launch_bounds__(256) csplit_k(const float* __restrict__ c,
                                                bf16* __restrict__ h, bf16* __restrict__ l)
{
    const int i = blockIdx.x * 256 + threadIdx.x;   // 32768
    bf16 hh, ll;
    split2(c[i], hh, ll);
    h[i] = hh;
    l[i] = ll;
}

// ============================================================
// inv_d = 1/(||k||^2 + 1e-6); one warp per token.
// ============================================================
__global__ void __launch_bounds__(256) norms_k(const float* __restrict__ kall,
                                               float* __restrict__ invd)
{
    const int row = blockIdx.x * 8 + (threadIdx.x >> 5);
    const int ln = threadIdx.x & 31;
    const float* p = kall + (size_t)row * HID;
    float4 a0 = *(const float4*)(p + ln * 8);
    float4 a1 = *(const float4*)(p + ln * 8 + 4);
    float4 b0 = *(const float4*)(p + HALF_ + ln * 8);
    float4 b1 = *(const float4*)(p + HALF_ + ln * 8 + 4);
    float s0 = a0.x*a0.x + a0.y*a0.y + a0.z*a0.z + a0.w*a0.w
             + a1.x*a1.x + a1.y*a1.y + a1.z*a1.z + a1.w*a1.w;
    float s1 = b0.x*b0.x + b0.y*b0.y + b0.z*b0.z + b0.w*b0.w
             + b1.x*b1.x + b1.y*b1.y + b1.z*b1.z + b1.w*b1.w;
#pragma unroll
    for (int o = 16; o; o >>= 1) {
        s0 += __shfl_xor_sync(0xffffffffu, s0, o);
        s1 += __shfl_xor_sync(0xffffffffu, s1, o);
    }
    if (ln == 0) {
        invd[(size_t)row * 2 + 0] = 1.f / (s0 + 1e-6f);
        invd[(size_t)row * 2 + 1] = 1.f / (s1 + 1e-6f);
    }
}

// ============================================================
// Backward vector scan (one warp per (batch, half) chain).
// ============================================================
__global__ void __launch_bounds__(32) scan_k(const float* __restrict__ kall,
                                             const float* __restrict__ invd,
                                             float* __restrict__ cbuf)
{
    const int chain = blockIdx.x;
    const int b = chain >> 1, wh = chain & 1;
    const int ln = threadIdx.x;
    const float* base = kall + (size_t)b * SEQL * HID + wh * HALF_ + ln * 8;

    float u[8], acc[8];
    {
        float4 q0 = *(const float4*)(base + (size_t)(SEQL - 1) * HID);
        float4 q1 = *(const float4*)(base + (size_t)(SEQL - 1) * HID + 4);
        u[0]=q0.x; u[1]=q0.y; u[2]=q0.z; u[3]=q0.w;
        u[4]=q1.x; u[5]=q1.y; u[6]=q1.z; u[7]=q1.w;
    }
#pragma unroll
    for (int j = 0; j < 8; j++) acc[j] = 0.f;

    float kc[8];
    {
        float4 t0 = *(const float4*)(base + (size_t)(SEQL - 2) * HID);
        float4 t1 = *(const float4*)(base + (size_t)(SEQL - 2) * HID + 4);
        kc[0]=t0.x; kc[1]=t0.y; kc[2]=t0.z; kc[3]=t0.w;
        kc[4]=t1.x; kc[5]=t1.y; kc[6]=t1.z; kc[7]=t1.w;
    }

    for (int t = SEQL - 2; t >= 0; --t) {
        float kn[8] = {0,0,0,0,0,0,0,0};
        if (t > 0) {
            float4 t0 = *(const float4*)(base + (size_t)(t - 1) * HID);
            float4 t1 = *(const float4*)(base + (size_t)(t - 1) * HID + 4);
            kn[0]=t0.x; kn[1]=t0.y; kn[2]=t0.z; kn[3]=t0.w;
            kn[4]=t1.x; kn[5]=t1.y; kn[6]=t1.z; kn[7]=t1.w;
        }
        const float id = invd[((size_t)b * SEQL + t) * 2 + wh];
        float p0 = u[0]*kc[0] + u[1]*kc[1];
        float p1 = u[2]*kc[2] + u[3]*kc[3];
        float p2 = u[4]*kc[4] + u[5]*kc[5];
        float p3 = u[6]*kc[6] + u[7]*kc[7];
        float s = (p0 + p1) + (p2 + p3);
#pragma unroll
        for (int o = 16; o; o >>= 1) s += __shfl_xor_sync(0xffffffffu, s, o);
        const float w = wh ? (float)(t + 1) * (1.f / 1024.f) : 1.f;
        const float ws = w * s;
        const float us = ws * id;
#pragma unroll
        for (int j = 0; j < 8; j++) {
            acc[j] += ws * kc[j];
            u[j]   -= us * kc[j];
        }
#pragma unroll
        for (int j = 0; j < 8; j++) kc[j] = kn[j];
    }
    float4 o0 = make_float4(acc[0], acc[1], acc[2], acc[3]);
    float4 o1 = make_float4(acc[4], acc[5], acc[6], acc[7]);
    *(float4*)(cbuf + (size_t)b * HID + wh * HALF_ + ln * 8) = o0;
    *(float4*)(cbuf + (size_t)b * HID + wh * HALF_ + ln * 8 + 4) = o1;
}

// ============================================================
extern "C" void kernel_launch(void* const* d_in, const int* in_sizes, int n_in,
                              void* d_out, int out_size)
{
    const int*   seq   = (const int*)d_in[0];
    const float* embed = (const float*)d_in[1];
    const float* w1    = (const float*)d_in[2];
    const float* b1    = (const float*)d_in[3];
    const float* w2    = (const float*)d_in[4];
    const float* b2    = (const float*)d_in[5];
    const float* lng   = (const float*)d_in[6];
    const float* lnb   = (const float*)d_in[7];
    const float* sw    = (const float*)d_in[8];
    const float* sb    = (const float*)d_in[9];
    const float* ew    = (const float*)d_in[10];
    const float* eb    = (const float*)d_in[11];
    const float* ow    = (const float*)d_in[12];
    const float* ob    = (const float*)d_in[13];
    float* out = (float*)d_out;

    static bool init = false;
    static bf16 *ah, *al, *h1h, *h1l, *hh, *hl, *w1h, *w1l, *w2h, *w2l,
                *wph, *wpl, *owh, *owl, *ch, *cl;
    static float *xb, *kb, *bp, *ivd, *cb;
    if (!init) {
        cudaGetSymbolAddress((void**)&ah,  g_ah);   cudaGetSymbolAddress((void**)&al,  g_al);
        cudaGetSymbolAddress((void**)&h1h, g_h1h);  cudaGetSymbolAddress((void**)&h1l, g_h1l);
        cudaGetSymbolAddress((void**)&hh,  g_hh);   cudaGetSymbolAddress((void**)&hl,  g_hl);
        cudaGetSymbolAddress((void**)&w1h, g_w1h);  cudaGetSymbolAddress((void**)&w1l, g_w1l);
        cudaGetSymbolAddress((void**)&w2h, g_w2h);  cudaGetSymbolAddress((void**)&w2l, g_w2l);
        cudaGetSymbolAddress((void**)&wph, g_wph);  cudaGetSymbolAddress((void**)&wpl, g_wpl);
        cudaGetSymbolAddress((void**)&owh, g_owh);  cudaGetSymbolAddress((void**)&owl, g_owl);
        cudaGetSymbolAddress((void**)&ch,  g_ch);   cudaGetSymbolAddress((void**)&cl,  g_cl);
        cudaGetSymbolAddress((void**)&xb,  g_x);
        cudaGetSymbolAddress((void**)&kb,  g_k);
        cudaGetSymbolAddress((void**)&bp,  g_bproj);
        cudaGetSymbolAddress((void**)&ivd, g_invd);
        cudaGetSymbolAddress((void**)&cb,  g_c);
        init = true;
    }

    // weight transpose + split (B operands are [N,K] K-major)
    tsplit_k<<<dim3(FF / 32, HID / 32), 256>>>(w1, HID, FF, w1h, w1l);
    tsplit_k<<<dim3(HID / 32, FF / 32), 256>>>(w2, FF, HID, w2h, w2l);
    tsplit_k<<<dim3(HALF_ / 32, HID / 32), 256>>>(sw, HID, HALF_, wph, wpl);
    tsplit_k<<<dim3(HALF_ / 32, HID / 32), 256>>>(ew, HID, HALF_, wph + (size_t)HALF_ * HID,
                                                  wpl + (size_t)HALF_ * HID);
    tsplit_k<<<dim3(VOC / 32, HID / 32), 256>>>(ow, HID, VOC, owh, owl);
    bpack_k<<<2, 256>>>(sb, eb);

    // A operand for GEMM1: gathered embeddings, split
    gsplit_k<<<TOK * 64 / 256, 256>>>(seq, embed, ah, al);

    // GEMM1: relu(e @ w1 + b1) -> h1 (bf16 hi/lo)   [65536 x 1024, K=512]
    mma_gemm<0><<<dim3(FF / 128, TOK / 128), 256>>>(
        TOK, FF, HID, ah, al, w1h, w1l, b1, nullptr, h1h, h1l, nullptr, nullptr);

    // GEMM2: x = h1 @ w2 + b2 + e  -> fp32          [65536 x 512, K=1024]
    mma_gemm<1><<<dim3(HID / 128, TOK / 128), 256>>>(
        TOK, HID, FF, h1h, h1l, w2h, w2l, b2, xb, nullptr, nullptr, seq, embed);

    // LayerNorm -> h (bf16 hi/lo)
    ln_split_k<<<TOK / 8, 256>>>(xb, lng, lnb, hh, hl);

    // GEMM3: k = h @ [sem|epi] + bias -> fp32       [65536 x 512, K=512]
    mma_gemm<2><<<dim3(HID / 128, TOK / 128), 256>>>(
        TOK, HID, HID, hh, hl, wph, wpl, bp, kb, nullptr, nullptr, nullptr, nullptr);

    // norms + backward scan
    norms_k<<<TOK / 8, 256>>>(kb, ivd);
    scan_k<<<128, 32>>>(kb, ivd, cb);

    // split c for final GEMM
    csplit_k<<<BATCH * HID / 256, 256>>>(cb, ch, cl);

    // GEMM4: out = c @ out_w + out_b                [64 x 32000, K=512]
    mma_gemm<2><<<dim3(VOC / 128, 1), 256>>>(
        BATCH, VOC, HID, ch, cl, owh, owl, ob, out, nullptr, nullptr, nullptr, nullptr);
}

// round 5
// speedup vs baseline: 2.7902x; 1.2067x over previous
#include <cuda_runtime.h>
#include <cuda_bf16.h>
#include <cstdint>

// Problem constants
#define TOK   65536      // B*L
#define BATCH 64
#define SEQL  1024
#define HID   512
#define FF    1024
#define HALF_ 256
#define VOC   32000

typedef __nv_bfloat16 bf16;

__device__ __forceinline__ uint32_t smem_u32(const void* p) {
    uint32_t a;
    asm("{ .reg .u64 t; cvta.to.shared.u64 t, %1; cvt.u32.u64 %0, t; }" : "=r"(a) : "l"(p));
    return a;
}
#define SW128(o) ((o) ^ (((o) >> 3) & 0x70))

__device__ __forceinline__ void ldsm4(uint32_t* r, uint32_t a) {
    asm volatile("ldmatrix.sync.aligned.m8n8.x4.shared.b16 {%0,%1,%2,%3}, [%4];"
        : "=r"(r[0]), "=r"(r[1]), "=r"(r[2]), "=r"(r[3]) : "r"(a));
}
__device__ __forceinline__ void ldsm2(uint32_t* r, uint32_t a) {
    asm volatile("ldmatrix.sync.aligned.m8n8.x2.shared.b16 {%0,%1}, [%2];"
        : "=r"(r[0]), "=r"(r[1]) : "r"(a));
}
__device__ __forceinline__ void mma16816(float* c, const uint32_t* a, const uint32_t* b) {
    asm volatile("mma.sync.aligned.m16n8k16.row.col.f32.bf16.bf16.f32 "
        "{%0,%1,%2,%3}, {%4,%5,%6,%7}, {%8,%9}, {%0,%1,%2,%3};"
        : "+f"(c[0]), "+f"(c[1]), "+f"(c[2]), "+f"(c[3])
        : "r"(a[0]), "r"(a[1]), "r"(a[2]), "r"(a[3]), "r"(b[0]), "r"(b[1]));
}
__device__ __forceinline__ void cp16(uint32_t dst, const void* src, bool pred) {
    const int sz = pred ? 16 : 0;
    asm volatile("cp.async.cg.shared.global [%0], [%1], 16, %2;"
        :: "r"(dst), "l"(src), "r"(sz) : "memory");
}
#define CP_COMMIT() asm volatile("cp.async.commit_group;" ::: "memory")
template<int N>
__device__ __forceinline__ void cp_wait() {
    asm volatile("cp.async.wait_group %0;" :: "n"(N) : "memory");
}

__device__ __forceinline__ void split2(float x, bf16& h, bf16& l) {
    h = __float2bfloat16(x);
    l = __float2bfloat16(x - __bfloat162float(h));
}

// -------- scratch (device globals) --------
__device__ bf16  g_ah[(size_t)TOK * HID],  g_al[(size_t)TOK * HID];
__device__ bf16  g_h1h[(size_t)TOK * FF],  g_h1l[(size_t)TOK * FF];
__device__ bf16  g_hh[(size_t)TOK * HID],  g_hl[(size_t)TOK * HID];
__device__ float g_x[(size_t)TOK * HID];
__device__ float g_k[(size_t)TOK * HID];
__device__ bf16  g_w1h[(size_t)FF * HID],  g_w1l[(size_t)FF * HID];
__device__ bf16  g_w2h[(size_t)HID * FF],  g_w2l[(size_t)HID * FF];
__device__ bf16  g_wph[(size_t)HID * HID], g_wpl[(size_t)HID * HID];
__device__ bf16  g_owh[(size_t)VOC * HID], g_owl[(size_t)VOC * HID];
__device__ float g_bproj[HID];
__device__ float g_invd[(size_t)TOK * 2];
__device__ float g_c[BATCH * HID];
__device__ bf16  g_ch[BATCH * HID], g_cl[BATCH * HID];

// ============================================================
// mma.sync split-bf16 GEMM, cp.async 2-stage pipeline.
// C[M,N] = A[M,K] @ B^T;  A [M,K] K-major hi/lo bf16, B [N,K] K-major hi/lo.
// C = Ah*Bh + Ah*Bl + Al*Bh (3-pass split).
// 128x128 CTA tile, BK=32, 256 threads (8 warps, 64x32 each).
// smem rows pack [hi 64B | lo 64B], SW128 swizzle; 2 stages x 32KB dynamic.
// EPI: 0 = relu(acc+bias) -> split bf16; 1 = acc+bias+embed[seq[m]] -> f32;
//      2 = acc+bias -> f32.
// ============================================================
#define GSTAGE 32768
#define GSMEM  (2 * GSTAGE)

template<int EPI>
__global__ void __launch_bounds__(256, 2) mma_gemm(
    int Mrows, int N, int K,
    const bf16* __restrict__ Ah, const bf16* __restrict__ Al,
    const bf16* __restrict__ Bh, const bf16* __restrict__ Bl,
    const float* __restrict__ bias,
    float* __restrict__ Cf, bf16* __restrict__ Chi, bf16* __restrict__ Clo,
    const int* __restrict__ seq, const float* __restrict__ embed)
{
    extern __shared__ __align__(1024) char smem[];
    const uint32_t sbase = smem_u32(smem);
    const int tid = threadIdx.x;
    const int bm = blockIdx.y * 128;
    const int bn = blockIdx.x * 128;
    const int wid = tid >> 5, lane = tid & 31;
    const int wm = (wid >> 2) * 64;     // warp row offset (0 / 64)
    const int wn = (wid & 3) * 32;      // warp col offset (0..96)
    const bool mguard = (Mrows & 127) != 0;

    // loader mapping: 2 threads per row, each 2x16B per half
    const int lrow = tid >> 1;
    const int lw = (tid & 1) * 2;
    const int am = bm + lrow;
    const bool av = !mguard || (am < Mrows);
    const int am_cl = av ? am : 0;
    const size_t aoff = (size_t)am_cl * K;
    const size_t boff = (size_t)(bn + lrow) * K;

    // ldmatrix lane addressing
    const int a_mi = lane >> 3;
    const int a_row = (lane & 7) + (a_mi & 1) * 8;
    const int a_kb = (a_mi >> 1) * 16;
    const int b_row = lane & 7;
    const int b_kb = ((lane >> 3) & 1) * 16;

    float c[16][4];
#pragma unroll
    for (int i = 0; i < 16; i++)
#pragma unroll
        for (int j = 0; j < 4; j++) c[i][j] = 0.f;

    const int NCH = K >> 5;

    // stage loader
    auto load_stage = [&](int s, int k0) {
        const uint32_t sA = sbase + s * GSTAGE;
        const uint32_t sB = sA + 16384;
#pragma unroll
        for (int it = 0; it < 2; it++) {
            const int word = lw + it;
            const uint32_t soh = SW128((uint32_t)(lrow * 128 + word * 16));
            const uint32_t sol = SW128((uint32_t)(lrow * 128 + 64 + word * 16));
            const size_t ko = (size_t)(k0 + word * 8);
            cp16(sA + soh, Ah + aoff + ko, av);
            cp16(sA + sol, Al + aoff + ko, av);
            cp16(sB + soh, Bh + boff + ko, true);
            cp16(sB + sol, Bl + boff + ko, true);
        }
    };

    load_stage(0, 0);
    CP_COMMIT();

    for (int ch = 0; ch < NCH; ch++) {
        const int s = ch & 1;
        if (ch + 1 < NCH) {
            load_stage((ch + 1) & 1, (ch + 1) * 32);
            CP_COMMIT();
            cp_wait<1>();
        } else {
            cp_wait<0>();
        }
        __syncthreads();
        const uint32_t sAu = sbase + s * GSTAGE;
        const uint32_t sBu = sAu + 16384;
        // ---- compute: 2 k16 steps, 3 passes each ----
#pragma unroll
        for (int k16 = 0; k16 < 2; k16++) {
            const int kb = k16 * 32;
            uint32_t bh[4][2], bl[4][2];
#pragma unroll
            for (int nt = 0; nt < 4; nt++) {
                const uint32_t rb = (uint32_t)((wn + nt * 8 + b_row) * 128);
                ldsm2(bh[nt], sBu + SW128(rb + kb + b_kb));
                ldsm2(bl[nt], sBu + SW128(rb + 64 + kb + b_kb));
            }
            uint32_t a[4][4];
#pragma unroll
            for (int mt = 0; mt < 4; mt++)
                ldsm4(a[mt], sAu + SW128((uint32_t)((wm + mt * 16 + a_row) * 128) + kb + a_kb));
#pragma unroll
            for (int mt = 0; mt < 4; mt++)
#pragma unroll
                for (int nt = 0; nt < 4; nt++) {
                    mma16816(c[mt * 4 + nt], a[mt], bh[nt]);
                    mma16816(c[mt * 4 + nt], a[mt], bl[nt]);
                }
            // lo(A) x hi(B)
#pragma unroll
            for (int mt = 0; mt < 4; mt++)
                ldsm4(a[mt], sAu + SW128((uint32_t)((wm + mt * 16 + a_row) * 128) + 64 + kb + a_kb));
#pragma unroll
            for (int mt = 0; mt < 4; mt++)
#pragma unroll
                for (int nt = 0; nt < 4; nt++)
                    mma16816(c[mt * 4 + nt], a[mt], bh[nt]);
        }
        __syncthreads();
    }

    // ---- epilogue ----
    const int mrow = lane >> 2;
    const int mcol = (lane & 3) * 2;
#pragma unroll
    for (int mt = 0; mt < 4; mt++) {
        const int r0 = bm + wm + mt * 16 + mrow;
        const int r1 = r0 + 8;
        const bool v0 = !mguard || (r0 < Mrows);
        const bool v1 = !mguard || (r1 < Mrows);
        const float* e0 = nullptr;
        const float* e1 = nullptr;
        if (EPI == 1) {
            if (v0) e0 = embed + (size_t)seq[r0] * HID;
            if (v1) e1 = embed + (size_t)seq[r1] * HID;
        }
#pragma unroll
        for (int nt = 0; nt < 4; nt++) {
            const int col = bn + wn + nt * 8 + mcol;
            float* cc = c[mt * 4 + nt];
            const float b0v = bias[col], b1v = bias[col + 1];
            float x0 = cc[0] + b0v, x1 = cc[1] + b1v;
            float x2 = cc[2] + b0v, x3 = cc[3] + b1v;
            if (EPI == 0) {
                x0 = fmaxf(x0, 0.f); x1 = fmaxf(x1, 0.f);
                x2 = fmaxf(x2, 0.f); x3 = fmaxf(x3, 0.f);
                bf16 h0, l0, h1, l1;
                if (v0) {
                    split2(x0, h0, l0); split2(x1, h1, l1);
                    __nv_bfloat162 ph; ph.x = h0; ph.y = h1;
                    __nv_bfloat162 pl; pl.x = l0; pl.y = l1;
                    *(__nv_bfloat162*)(Chi + (size_t)r0 * N + col) = ph;
                    *(__nv_bfloat162*)(Clo + (size_t)r0 * N + col) = pl;
                }
                if (v1) {
                    split2(x2, h0, l0); split2(x3, h1, l1);
                    __nv_bfloat162 ph; ph.x = h0; ph.y = h1;
                    __nv_bfloat162 pl; pl.x = l0; pl.y = l1;
                    *(__nv_bfloat162*)(Chi + (size_t)r1 * N + col) = ph;
                    *(__nv_bfloat162*)(Clo + (size_t)r1 * N + col) = pl;
                }
            } else {
                if (EPI == 1) {
                    if (v0) { x0 += e0[col]; x1 += e0[col + 1]; }
                    if (v1) { x2 += e1[col]; x3 += e1[col + 1]; }
                }
                if (v0) *(float2*)(Cf + (size_t)r0 * N + col) = make_float2(x0, x1);
                if (v1) *(float2*)(Cf + (size_t)r1 * N + col) = make_float2(x2, x3);
            }
        }
    }
}

// ============================================================
// gather + split:  Ahi/Alo[m] = split(embed[seq[m]])
// ============================================================
__global__ void __launch_bounds__(256) gsplit_k(const int* __restrict__ seq,
                                                const float* __restrict__ embed,
                                                bf16* __restrict__ hi, bf16* __restrict__ lo)
{
    const size_t idx = (size_t)blockIdx.x * 256 + threadIdx.x;   // TOK*64
    const int t = (int)(idx >> 6), c = (int)(idx & 63) * 8;
    const float* p = embed + (size_t)seq[t] * HID + c;
    float4 a = *(const float4*)p;
    float4 b = *(const float4*)(p + 4);
    float vv[8] = {a.x, a.y, a.z, a.w, b.x, b.y, b.z, b.w};
    const size_t ob = (size_t)t * HID + c;
#pragma unroll
    for (int j = 0; j < 8; j += 2) {
        bf16 h0, l0, h1, l1;
        split2(vv[j], h0, l0);
        split2(vv[j + 1], h1, l1);
        __nv_bfloat162 ph; ph.x = h0; ph.y = h1;
        __nv_bfloat162 pl; pl.x = l0; pl.y = l1;
        *(__nv_bfloat162*)(hi + ob + j) = ph;
        *(__nv_bfloat162*)(lo + ob + j) = pl;
    }
}

// ============================================================
// Tiled transpose + split: W[K,N] fp32 -> out[N,K] hi/lo bf16.
// ============================================================
__global__ void __launch_bounds__(256) tsplit_k(const float* __restrict__ W, int K, int N,
                                                bf16* __restrict__ ht, bf16* __restrict__ lt)
{
    __shared__ float t[32][33];
    const int tx = threadIdx.x & 31, ty = threadIdx.x >> 5;
    const int n0 = blockIdx.x * 32, k0 = blockIdx.y * 32;
#pragma unroll
    for (int i = 0; i < 4; i++)
        t[ty + 8 * i][tx] = W[(size_t)(k0 + ty + 8 * i) * N + n0 + tx];
    __syncthreads();
#pragma unroll
    for (int i = 0; i < 4; i++) {
        float v = t[tx][ty + 8 * i];
        bf16 h, l;
        split2(v, h, l);
        const size_t o = (size_t)(n0 + ty + 8 * i) * K + k0 + tx;
        ht[o] = h;
        lt[o] = l;
    }
}

// ============================================================
// LayerNorm (warp per row) + split output to bf16 hi/lo.
// ============================================================
__global__ void __launch_bounds__(256) ln_split_k(const float* __restrict__ x,
                                                  const float* __restrict__ g,
                                                  const float* __restrict__ b,
                                                  bf16* __restrict__ hh, bf16* __restrict__ hl)
{
    const int row = blockIdx.x * 8 + (threadIdx.x >> 5);
    const int ln = threadIdx.x & 31;
    const float* xr = x + (size_t)row * HID + ln * 16;
    float v[16];
    *(float4*)&v[0]  = ((const float4*)xr)[0];
    *(float4*)&v[4]  = ((const float4*)xr)[1];
    *(float4*)&v[8]  = ((const float4*)xr)[2];
    *(float4*)&v[12] = ((const float4*)xr)[3];
    float s = 0.f;
#pragma unroll
    for (int j = 0; j < 16; j++) s += v[j];
#pragma unroll
    for (int o = 16; o; o >>= 1) s += __shfl_xor_sync(0xffffffffu, s, o);
    const float mean = s * (1.f / 512.f);
    float q = 0.f;
#pragma unroll
    for (int j = 0; j < 16; j++) { float d = v[j] - mean; q += d * d; }
#pragma unroll
    for (int o = 16; o; o >>= 1) q += __shfl_xor_sync(0xffffffffu, q, o);
    const float r = rsqrtf(q * (1.f / 512.f) + 1e-5f);
    const size_t ob = (size_t)row * HID + ln * 16;
#pragma unroll
    for (int j = 0; j < 16; j += 2) {
        const int c0 = ln * 16 + j;
        float y0 = (v[j] - mean) * r * g[c0] + b[c0];
        float y1 = (v[j + 1] - mean) * r * g[c0 + 1] + b[c0 + 1];
        bf16 h0, l0, h1, l1;
        split2(y0, h0, l0);
        split2(y1, h1, l1);
        __nv_bfloat162 ph; ph.x = h0; ph.y = h1;
        __nv_bfloat162 pl; pl.x = l0; pl.y = l1;
        *(__nv_bfloat162*)(hh + ob + j) = ph;
        *(__nv_bfloat162*)(hl + ob + j) = pl;
    }
}

// ============================================================
__global__ void bpack_k(const float* __restrict__ sb, const float* __restrict__ eb)
{
    const int i = blockIdx.x * 256 + threadIdx.x;
    if (i < HID) g_bproj[i] = (i < HALF_) ? sb[i] : eb[i - HALF_];
}

__global__ void __launch_bounds__(256) csplit_k(const float* __restrict__ c,
                                                bf16* __restrict__ h, bf16* __restrict__ l)
{
    const int i = blockIdx.x * 256 + threadIdx.x;   // 32768
    bf16 hh, ll;
    split2(c[i], hh, ll);
    h[i] = hh;
    l[i] = ll;
}

// ============================================================
// inv_d = 1/(||k||^2 + 1e-6); one warp per token.
// ============================================================
__global__ void __launch_bounds__(256) norms_k(const float* __restrict__ kall,
                                               float* __restrict__ invd)
{
    const int row = blockIdx.x * 8 + (threadIdx.x >> 5);
    const int ln = threadIdx.x & 31;
    const float* p = kall + (size_t)row * HID;
    float4 a0 = *(const float4*)(p + ln * 8);
    float4 a1 = *(const float4*)(p + ln * 8 + 4);
    float4 b0 = *(const float4*)(p + HALF_ + ln * 8);
    float4 b1 = *(const float4*)(p + HALF_ + ln * 8 + 4);
    float s0 = a0.x*a0.x + a0.y*a0.y + a0.z*a0.z + a0.w*a0.w
             + a1.x*a1.x + a1.y*a1.y + a1.z*a1.z + a1.w*a1.w;
    float s1 = b0.x*b0.x + b0.y*b0.y + b0.z*b0.z + b0.w*b0.w
             + b1.x*b1.x + b1.y*b1.y + b1.z*b1.z + b1.w*b1.w;
#pragma unroll
    for (int o = 16; o; o >>= 1) {
        s0 += __shfl_xor_sync(0xffffffffu, s0, o);
        s1 += __shfl_xor_sync(0xffffffffu, s1, o);
    }
    if (ln == 0) {
        invd[(size_t)row * 2 + 0] = 1.f / (s0 + 1e-6f);
        invd[(size_t)row * 2 + 1] = 1.f / (s1 + 1e-6f);
    }
}

// ============================================================
// Backward vector scan (one warp per (batch, half) chain).
// ============================================================
__global__ void __launch_bounds__(32) scan_k(const float* __restrict__ kall,
                                             const float* __restrict__ invd,
                                             float* __restrict__ cbuf)
{
    const int chain = blockIdx.x;
    const int b = chain >> 1, wh = chain & 1;
    const int ln = threadIdx.x;
    const float* base = kall + (size_t)b * SEQL * HID + wh * HALF_ + ln * 8;

    float u[8], acc[8];
    {
        float4 q0 = *(const float4*)(base + (size_t)(SEQL - 1) * HID);
        float4 q1 = *(const float4*)(base + (size_t)(SEQL - 1) * HID + 4);
        u[0]=q0.x; u[1]=q0.y; u[2]=q0.z; u[3]=q0.w;
        u[4]=q1.x; u[5]=q1.y; u[6]=q1.z; u[7]=q1.w;
    }
#pragma unroll
    for (int j = 0; j < 8; j++) acc[j] = 0.f;

    float kc[8];
    {
        float4 t0 = *(const float4*)(base + (size_t)(SEQL - 2) * HID);
        float4 t1 = *(const float4*)(base + (size_t)(SEQL - 2) * HID + 4);
        kc[0]=t0.x; kc[1]=t0.y; kc[2]=t0.z; kc[3]=t0.w;
        kc[4]=t1.x; kc[5]=t1.y; kc[6]=t1.z; kc[7]=t1.w;
    }

    for (int t = SEQL - 2; t >= 0; --t) {
        float kn[8] = {0,0,0,0,0,0,0,0};
        if (t > 0) {
            float4 t0 = *(const float4*)(base + (size_t)(t - 1) * HID);
            float4 t1 = *(const float4*)(base + (size_t)(t - 1) * HID + 4);
            kn[0]=t0.x; kn[1]=t0.y; kn[2]=t0.z; kn[3]=t0.w;
            kn[4]=t1.x; kn[5]=t1.y; kn[6]=t1.z; kn[7]=t1.w;
        }
        const float id = invd[((size_t)b * SEQL + t) * 2 + wh];
        float p0 = u[0]*kc[0] + u[1]*kc[1];
        float p1 = u[2]*kc[2] + u[3]*kc[3];
        float p2 = u[4]*kc[4] + u[5]*kc[5];
        float p3 = u[6]*kc[6] + u[7]*kc[7];
        float s = (p0 + p1) + (p2 + p3);
#pragma unroll
        for (int o = 16; o; o >>= 1) s += __shfl_xor_sync(0xffffffffu, s, o);
        const float w = wh ? (float)(t + 1) * (1.f / 1024.f) : 1.f;
        const float ws = w * s;
        const float us = ws * id;
#pragma unroll
        for (int j = 0; j < 8; j++) {
            acc[j] += ws * kc[j];
            u[j]   -= us * kc[j];
        }
#pragma unroll
        for (int j = 0; j < 8; j++) kc[j] = kn[j];
    }
    float4 o0 = make_float4(acc[0], acc[1], acc[2], acc[3]);
    float4 o1 = make_float4(acc[4], acc[5], acc[6], acc[7]);
    *(float4*)(cbuf + (size_t)b * HID + wh * HALF_ + ln * 8) = o0;
    *(float4*)(cbuf + (size_t)b * HID + wh * HALF_ + ln * 8 + 4) = o1;
}

// ============================================================
extern "C" void kernel_launch(void* const* d_in, const int* in_sizes, int n_in,
                              void* d_out, int out_size)
{
    const int*   seq   = (const int*)d_in[0];
    const float* embed = (const float*)d_in[1];
    const float* w1    = (const float*)d_in[2];
    const float* b1    = (const float*)d_in[3];
    const float* w2    = (const float*)d_in[4];
    const float* b2    = (const float*)d_in[5];
    const float* lng   = (const float*)d_in[6];
    const float* lnb   = (const float*)d_in[7];
    const float* sw    = (const float*)d_in[8];
    const float* sb    = (const float*)d_in[9];
    const float* ew    = (const float*)d_in[10];
    const float* eb    = (const float*)d_in[11];
    const float* ow    = (const float*)d_in[12];
    const float* ob    = (const float*)d_in[13];
    float* out = (float*)d_out;

    static bool init = false;
    static bf16 *ah, *al, *h1h, *h1l, *hh, *hl, *w1h, *w1l, *w2h, *w2l,
                *wph, *wpl, *owh, *owl, *ch, *cl;
    static float *xb, *kb, *bp, *ivd, *cb;
    if (!init) {
        cudaGetSymbolAddress((void**)&ah,  g_ah);   cudaGetSymbolAddress((void**)&al,  g_al);
        cudaGetSymbolAddress((void**)&h1h, g_h1h);  cudaGetSymbolAddress((void**)&h1l, g_h1l);
        cudaGetSymbolAddress((void**)&hh,  g_hh);   cudaGetSymbolAddress((void**)&hl,  g_hl);
        cudaGetSymbolAddress((void**)&w1h, g_w1h);  cudaGetSymbolAddress((void**)&w1l, g_w1l);
        cudaGetSymbolAddress((void**)&w2h, g_w2h);  cudaGetSymbolAddress((void**)&w2l, g_w2l);
        cudaGetSymbolAddress((void**)&wph, g_wph);  cudaGetSymbolAddress((void**)&wpl, g_wpl);
        cudaGetSymbolAddress((void**)&owh, g_owh);  cudaGetSymbolAddress((void**)&owl, g_owl);
        cudaGetSymbolAddress((void**)&ch,  g_ch);   cudaGetSymbolAddress((void**)&cl,  g_cl);
        cudaGetSymbolAddress((void**)&xb,  g_x);
        cudaGetSymbolAddress((void**)&kb,  g_k);
        cudaGetSymbolAddress((void**)&bp,  g_bproj);
        cudaGetSymbolAddress((void**)&ivd, g_invd);
        cudaGetSymbolAddress((void**)&cb,  g_c);
        cudaFuncSetAttribute(mma_gemm<0>, cudaFuncAttributeMaxDynamicSharedMemorySize, GSMEM);
        cudaFuncSetAttribute(mma_gemm<1>, cudaFuncAttributeMaxDynamicSharedMemorySize, GSMEM);
        cudaFuncSetAttribute(mma_gemm<2>, cudaFuncAttributeMaxDynamicSharedMemorySize, GSMEM);
        init = true;
    }

    // weight transpose + split (B operands are [N,K] K-major)
    tsplit_k<<<dim3(FF / 32, HID / 32), 256>>>(w1, HID, FF, w1h, w1l);
    tsplit_k<<<dim3(HID / 32, FF / 32), 256>>>(w2, FF, HID, w2h, w2l);
    tsplit_k<<<dim3(HALF_ / 32, HID / 32), 256>>>(sw, HID, HALF_, wph, wpl);
    tsplit_k<<<dim3(HALF_ / 32, HID / 32), 256>>>(ew, HID, HALF_, wph + (size_t)HALF_ * HID,
                                                  wpl + (size_t)HALF_ * HID);
    tsplit_k<<<dim3(VOC / 32, HID / 32), 256>>>(ow, HID, VOC, owh, owl);
    bpack_k<<<2, 256>>>(sb, eb);

    // A operand for GEMM1: gathered embeddings, split
    gsplit_k<<<TOK * 64 / 256, 256>>>(seq, embed, ah, al);

    // GEMM1: relu(e @ w1 + b1) -> h1 (bf16 hi/lo)   [65536 x 1024, K=512]
    mma_gemm<0><<<dim3(FF / 128, TOK / 128), 256, GSMEM>>>(
        TOK, FF, HID, ah, al, w1h, w1l, b1, nullptr, h1h, h1l, nullptr, nullptr);

    // GEMM2: x = h1 @ w2 + b2 + e  -> fp32          [65536 x 512, K=1024]
    mma_gemm<1><<<dim3(HID / 128, TOK / 128), 256, GSMEM>>>(
        TOK, HID, FF, h1h, h1l, w2h, w2l, b2, xb, nullptr, nullptr, seq, embed);

    // LayerNorm -> h (bf16 hi/lo)
    ln_split_k<<<TOK / 8, 256>>>(xb, lng, lnb, hh, hl);

    // GEMM3: k = h @ [sem|epi] + bias -> fp32       [65536 x 512, K=512]
    mma_gemm<2><<<dim3(HID / 128, TOK / 128), 256, GSMEM>>>(
        TOK, HID, HID, hh, hl, wph, wpl, bp, kb, nullptr, nullptr, nullptr, nullptr);

    // norms + backward scan
    norms_k<<<TOK / 8, 256>>>(kb, ivd);
    scan_k<<<128, 32>>>(kb, ivd, cb);

    // split c for final GEMM
    csplit_k<<<BATCH * HID / 256, 256>>>(cb, ch, cl);

    // GEMM4: out = c @ out_w + out_b                [64 x 32000, K=512]
    mma_gemm<2><<<dim3(VOC / 128, 1), 256, GSMEM>>>(
        BATCH, VOC, HID, ch, cl, owh, owl, ob, out, nullptr, nullptr, nullptr, nullptr);
}

// round 6
// speedup vs baseline: 2.9841x; 1.0695x over previous
#include <cuda_runtime.h>
#include <cuda_bf16.h>
#include <cstdint>

// Problem constants
#define TOK   65536      // B*L
#define BATCH 64
#define SEQL  1024
#define HID   512
#define FF    1024
#define HALF_ 256
#define VOC   32000

typedef __nv_bfloat16 bf16;

__device__ __forceinline__ uint32_t smem_u32(const void* p) {
    uint32_t a;
    asm("{ .reg .u64 t; cvta.to.shared.u64 t, %1; cvt.u32.u64 %0, t; }" : "=r"(a) : "l"(p));
    return a;
}
#define SW128(o) ((o) ^ (((o) >> 3) & 0x70))

__device__ __forceinline__ void ldsm4(uint32_t* r, uint32_t a) {
    asm volatile("ldmatrix.sync.aligned.m8n8.x4.shared.b16 {%0,%1,%2,%3}, [%4];"
        : "=r"(r[0]), "=r"(r[1]), "=r"(r[2]), "=r"(r[3]) : "r"(a));
}
__device__ __forceinline__ void mma16816(float* c, const uint32_t* a, const uint32_t* b) {
    asm volatile("mma.sync.aligned.m16n8k16.row.col.f32.bf16.bf16.f32 "
        "{%0,%1,%2,%3}, {%4,%5,%6,%7}, {%8,%9}, {%0,%1,%2,%3};"
        : "+f"(c[0]), "+f"(c[1]), "+f"(c[2]), "+f"(c[3])
        : "r"(a[0]), "r"(a[1]), "r"(a[2]), "r"(a[3]), "r"(b[0]), "r"(b[1]));
}
__device__ __forceinline__ void cp16(uint32_t dst, const void* src, bool pred) {
    const int sz = pred ? 16 : 0;
    asm volatile("cp.async.cg.shared.global [%0], [%1], 16, %2;"
        :: "r"(dst), "l"(src), "r"(sz) : "memory");
}
#define CP_COMMIT() asm volatile("cp.async.commit_group;" ::: "memory")
template<int N>
__device__ __forceinline__ void cp_wait() {
    asm volatile("cp.async.wait_group %0;" :: "n"(N) : "memory");
}

__device__ __forceinline__ void split2(float x, bf16& h, bf16& l) {
    h = __float2bfloat16(x);
    l = __float2bfloat16(x - __bfloat162float(h));
}

// -------- scratch (device globals) --------
__device__ bf16  g_ah[(size_t)TOK * HID],  g_al[(size_t)TOK * HID];
__device__ bf16  g_h1h[(size_t)TOK * FF],  g_h1l[(size_t)TOK * FF];
__device__ bf16  g_hh[(size_t)TOK * HID],  g_hl[(size_t)TOK * HID];
__device__ float g_x[(size_t)TOK * HID];
__device__ float g_k[(size_t)TOK * HID];
__device__ bf16  g_w1h[(size_t)FF * HID],  g_w1l[(size_t)FF * HID];
__device__ bf16  g_w2h[(size_t)HID * FF],  g_w2l[(size_t)HID * FF];
__device__ bf16  g_wph[(size_t)HID * HID], g_wpl[(size_t)HID * HID];
__device__ bf16  g_owh[(size_t)VOC * HID], g_owl[(size_t)VOC * HID];
__device__ float g_bproj[HID];
__device__ float g_invd[(size_t)TOK * 2];
__device__ float g_c[BATCH * HID];
__device__ bf16  g_ch[BATCH * HID], g_cl[BATCH * HID];

// ============================================================
// mma.sync split-bf16 GEMM, cp.async 3-stage pipeline.
// C[M,N] = A[M,K] @ B^T;  A [M,K] K-major hi/lo bf16, B [N,K] K-major hi/lo.
// C = Ah*Bh + Ah*Bl + Al*Bh (3-pass split).
// 128x128 CTA tile, BK=32, 256 threads (8 warps, 64x32 each).
// smem rows pack [hi 64B | lo 64B], SW128 swizzle; 3 stages x 32KB dynamic.
// One __syncthreads per chunk.
// EPI: 0 = relu(acc+bias) -> split bf16; 1 = acc+bias+embed[seq[m]] -> f32;
//      2 = acc+bias -> f32.
// ============================================================
#define GSTAGE 32768
#define NSTAGE 3
#define GSMEM  (NSTAGE * GSTAGE)

template<int EPI>
__global__ void __launch_bounds__(256, 2) mma_gemm(
    int Mrows, int N, int K,
    const bf16* __restrict__ Ah, const bf16* __restrict__ Al,
    const bf16* __restrict__ Bh, const bf16* __restrict__ Bl,
    const float* __restrict__ bias,
    float* __restrict__ Cf, bf16* __restrict__ Chi, bf16* __restrict__ Clo,
    const int* __restrict__ seq, const float* __restrict__ embed)
{
    extern __shared__ __align__(1024) char smem[];
    const uint32_t sbase = smem_u32(smem);
    const int tid = threadIdx.x;
    const int bm = blockIdx.y * 128;
    const int bn = blockIdx.x * 128;
    const int wid = tid >> 5, lane = tid & 31;
    const int wm = (wid >> 2) * 64;     // warp row offset (0 / 64)
    const int wn = (wid & 3) * 32;      // warp col offset (0..96)
    const bool mguard = (Mrows & 127) != 0;

    // loader mapping: 2 threads per row, each 2x16B per half
    const int lrow = tid >> 1;
    const int lw = (tid & 1) * 2;
    const int am = bm + lrow;
    const bool av = !mguard || (am < Mrows);
    const int am_cl = av ? am : 0;
    const size_t aoff = (size_t)am_cl * K;
    const size_t boff = (size_t)(bn + lrow) * K;

    // A ldmatrix lane addressing (m16 x k16 per x4)
    const int a_mi = lane >> 3;
    const int a_row = (lane & 7) + (a_mi & 1) * 8;
    const int a_kb = (a_mi >> 1) * 16;
    // B ldmatrix lane addressing (2 n8 tiles x 2 k-halves per x4)
    const int b_g = lane >> 3;                    // matrix group 0..3
    const int b_row = lane & 7;
    const int b_nt = b_g >> 1;                    // 0/1 within pair
    const int b_kh = (b_g & 1) * 16;              // k-half byte offset

    float c[16][4];
#pragma unroll
    for (int i = 0; i < 16; i++)
#pragma unroll
        for (int j = 0; j < 4; j++) c[i][j] = 0.f;

    const int NCH = K >> 5;

    // stage loader
    auto load_stage = [&](int s, int k0) {
        const uint32_t sA = sbase + s * GSTAGE;
        const uint32_t sB = sA + 16384;
#pragma unroll
        for (int it = 0; it < 2; it++) {
            const int word = lw + it;
            const uint32_t soh = SW128((uint32_t)(lrow * 128 + word * 16));
            const uint32_t sol = SW128((uint32_t)(lrow * 128 + 64 + word * 16));
            const size_t ko = (size_t)(k0 + word * 8);
            cp16(sA + soh, Ah + aoff + ko, av);
            cp16(sA + sol, Al + aoff + ko, av);
            cp16(sB + soh, Bh + boff + ko, true);
            cp16(sB + sol, Bl + boff + ko, true);
        }
    };

    load_stage(0, 0);
    CP_COMMIT();
    load_stage(1, 32);
    CP_COMMIT();

    int stage = 0;
    for (int ch = 0; ch < NCH; ch++) {
        if (ch + 1 < NCH) cp_wait<1>(); else cp_wait<0>();
        __syncthreads();
        if (ch + 2 < NCH) {
            int ns = stage + 2; if (ns >= NSTAGE) ns -= NSTAGE;
            load_stage(ns, (ch + 2) * 32);
            CP_COMMIT();
        }
        const uint32_t sAu = sbase + stage * GSTAGE;
        const uint32_t sBu = sAu + 16384;
        // ---- compute: 2 k16 steps, 3 passes each ----
#pragma unroll
        for (int k16 = 0; k16 < 2; k16++) {
            const int kb = k16 * 32;
            // B fragments: 2 x ldsm4 each for hi and lo
            uint32_t bh[2][4], bl[2][4];
#pragma unroll
            for (int p = 0; p < 2; p++) {
                const uint32_t rb = (uint32_t)((wn + (p * 2 + b_nt) * 8 + b_row) * 128);
                ldsm4(bh[p], sBu + SW128(rb + kb + b_kh));
                ldsm4(bl[p], sBu + SW128(rb + 64 + kb + b_kh));
            }
            uint32_t a[4][4];
#pragma unroll
            for (int mt = 0; mt < 4; mt++)
                ldsm4(a[mt], sAu + SW128((uint32_t)((wm + mt * 16 + a_row) * 128) + kb + a_kb));
#pragma unroll
            for (int mt = 0; mt < 4; mt++)
#pragma unroll
                for (int nt = 0; nt < 4; nt++) {
                    const uint32_t* bb = &bh[nt >> 1][(nt & 1) * 2];
                    const uint32_t* bbl = &bl[nt >> 1][(nt & 1) * 2];
                    mma16816(c[mt * 4 + nt], a[mt], bb);
                    mma16816(c[mt * 4 + nt], a[mt], bbl);
                }
            // lo(A) x hi(B)
#pragma unroll
            for (int mt = 0; mt < 4; mt++)
                ldsm4(a[mt], sAu + SW128((uint32_t)((wm + mt * 16 + a_row) * 128) + 64 + kb + a_kb));
#pragma unroll
            for (int mt = 0; mt < 4; mt++)
#pragma unroll
                for (int nt = 0; nt < 4; nt++)
                    mma16816(c[mt * 4 + nt], a[mt], &bh[nt >> 1][(nt & 1) * 2]);
        }
        if (++stage >= NSTAGE) stage = 0;
    }

    // ---- epilogue ----
    const int mrow = lane >> 2;
    const int mcol = (lane & 3) * 2;
#pragma unroll
    for (int mt = 0; mt < 4; mt++) {
        const int r0 = bm + wm + mt * 16 + mrow;
        const int r1 = r0 + 8;
        const bool v0 = !mguard || (r0 < Mrows);
        const bool v1 = !mguard || (r1 < Mrows);
        const float* e0 = nullptr;
        const float* e1 = nullptr;
        if (EPI == 1) {
            if (v0) e0 = embed + (size_t)seq[r0] * HID;
            if (v1) e1 = embed + (size_t)seq[r1] * HID;
        }
#pragma unroll
        for (int nt = 0; nt < 4; nt++) {
            const int col = bn + wn + nt * 8 + mcol;
            float* cc = c[mt * 4 + nt];
            const float b0v = bias[col], b1v = bias[col + 1];
            float x0 = cc[0] + b0v, x1 = cc[1] + b1v;
            float x2 = cc[2] + b0v, x3 = cc[3] + b1v;
            if (EPI == 0) {
                x0 = fmaxf(x0, 0.f); x1 = fmaxf(x1, 0.f);
                x2 = fmaxf(x2, 0.f); x3 = fmaxf(x3, 0.f);
                bf16 h0, l0, h1, l1;
                if (v0) {
                    split2(x0, h0, l0); split2(x1, h1, l1);
                    __nv_bfloat162 ph; ph.x = h0; ph.y = h1;
                    __nv_bfloat162 pl; pl.x = l0; pl.y = l1;
                    *(__nv_bfloat162*)(Chi + (size_t)r0 * N + col) = ph;
                    *(__nv_bfloat162*)(Clo + (size_t)r0 * N + col) = pl;
                }
                if (v1) {
                    split2(x2, h0, l0); split2(x3, h1, l1);
                    __nv_bfloat162 ph; ph.x = h0; ph.y = h1;
                    __nv_bfloat162 pl; pl.x = l0; pl.y = l1;
                    *(__nv_bfloat162*)(Chi + (size_t)r1 * N + col) = ph;
                    *(__nv_bfloat162*)(Clo + (size_t)r1 * N + col) = pl;
                }
            } else {
                if (EPI == 1) {
                    if (v0) { x0 += e0[col]; x1 += e0[col + 1]; }
                    if (v1) { x2 += e1[col]; x3 += e1[col + 1]; }
                }
                if (v0) *(float2*)(Cf + (size_t)r0 * N + col) = make_float2(x0, x1);
                if (v1) *(float2*)(Cf + (size_t)r1 * N + col) = make_float2(x2, x3);
            }
        }
    }
}

// ============================================================
// gather + split:  Ahi/Alo[m] = split(embed[seq[m]])
// ============================================================
__global__ void __launch_bounds__(256) gsplit_k(const int* __restrict__ seq,
                                                const float* __restrict__ embed,
                                                bf16* __restrict__ hi, bf16* __restrict__ lo)
{
    const size_t idx = (size_t)blockIdx.x * 256 + threadIdx.x;   // TOK*64
    const int t = (int)(idx >> 6), c = (int)(idx & 63) * 8;
    const float* p = embed + (size_t)seq[t] * HID + c;
    float4 a = *(const float4*)p;
    float4 b = *(const float4*)(p + 4);
    float vv[8] = {a.x, a.y, a.z, a.w, b.x, b.y, b.z, b.w};
    const size_t ob = (size_t)t * HID + c;
#pragma unroll
    for (int j = 0; j < 8; j += 2) {
        bf16 h0, l0, h1, l1;
        split2(vv[j], h0, l0);
        split2(vv[j + 1], h1, l1);
        __nv_bfloat162 ph; ph.x = h0; ph.y = h1;
        __nv_bfloat162 pl; pl.x = l0; pl.y = l1;
        *(__nv_bfloat162*)(hi + ob + j) = ph;
        *(__nv_bfloat162*)(lo + ob + j) = pl;
    }
}

// ============================================================
// Tiled transpose + split: W[K,N] fp32 -> out[N,K] hi/lo bf16.
// ============================================================
__global__ void __launch_bounds__(256) tsplit_k(const float* __restrict__ W, int K, int N,
                                                bf16* __restrict__ ht, bf16* __restrict__ lt)
{
    __shared__ float t[32][33];
    const int tx = threadIdx.x & 31, ty = threadIdx.x >> 5;
    const int n0 = blockIdx.x * 32, k0 = blockIdx.y * 32;
#pragma unroll
    for (int i = 0; i < 4; i++)
        t[ty + 8 * i][tx] = W[(size_t)(k0 + ty + 8 * i) * N + n0 + tx];
    __syncthreads();
#pragma unroll
    for (int i = 0; i < 4; i++) {
        float v = t[tx][ty + 8 * i];
        bf16 h, l;
        split2(v, h, l);
        const size_t o = (size_t)(n0 + ty + 8 * i) * K + k0 + tx;
        ht[o] = h;
        lt[o] = l;
    }
}

// ============================================================
// LayerNorm (warp per row) + split output to bf16 hi/lo.
// ============================================================
__global__ void __launch_bounds__(256) ln_split_k(const float* __restrict__ x,
                                                  const float* __restrict__ g,
                                                  const float* __restrict__ b,
                                                  bf16* __restrict__ hh, bf16* __restrict__ hl)
{
    const int row = blockIdx.x * 8 + (threadIdx.x >> 5);
    const int ln = threadIdx.x & 31;
    const float* xr = x + (size_t)row * HID + ln * 16;
    float v[16];
    *(float4*)&v[0]  = ((const float4*)xr)[0];
    *(float4*)&v[4]  = ((const float4*)xr)[1];
    *(float4*)&v[8]  = ((const float4*)xr)[2];
    *(float4*)&v[12] = ((const float4*)xr)[3];
    float s = 0.f;
#pragma unroll
    for (int j = 0; j < 16; j++) s += v[j];
#pragma unroll
    for (int o = 16; o; o >>= 1) s += __shfl_xor_sync(0xffffffffu, s, o);
    const float mean = s * (1.f / 512.f);
    float q = 0.f;
#pragma unroll
    for (int j = 0; j < 16; j++) { float d = v[j] - mean; q += d * d; }
#pragma unroll
    for (int o = 16; o; o >>= 1) q += __shfl_xor_sync(0xffffffffu, q, o);
    const float r = rsqrtf(q * (1.f / 512.f) + 1e-5f);
    const size_t ob = (size_t)row * HID + ln * 16;
#pragma unroll
    for (int j = 0; j < 16; j += 2) {
        const int c0 = ln * 16 + j;
        float y0 = (v[j] - mean) * r * g[c0] + b[c0];
        float y1 = (v[j + 1] - mean) * r * g[c0 + 1] + b[c0 + 1];
        bf16 h0, l0, h1, l1;
        split2(y0, h0, l0);
        split2(y1, h1, l1);
        __nv_bfloat162 ph; ph.x = h0; ph.y = h1;
        __nv_bfloat162 pl; pl.x = l0; pl.y = l1;
        *(__nv_bfloat162*)(hh + ob + j) = ph;
        *(__nv_bfloat162*)(hl + ob + j) = pl;
    }
}

// ============================================================
__global__ void bpack_k(const float* __restrict__ sb, const float* __restrict__ eb)
{
    const int i = blockIdx.x * 256 + threadIdx.x;
    if (i < HID) g_bproj[i] = (i < HALF_) ? sb[i] : eb[i - HALF_];
}

__global__ void __launch_bounds__(256) csplit_k(const float* __restrict__ c,
                                                bf16* __restrict__ h, bf16* __restrict__ l)
{
    const int i = blockIdx.x * 256 + threadIdx.x;   // 32768
    bf16 hh, ll;
    split2(c[i], hh, ll);
    h[i] = hh;
    l[i] = ll;
}

// ============================================================
// inv_d = 1/(||k||^2 + 1e-6); one warp per token.
// ============================================================
__global__ void __launch_bounds__(256) norms_k(const float* __restrict__ kall,
                                               float* __restrict__ invd)
{
    const int row = blockIdx.x * 8 + (threadIdx.x >> 5);
    const int ln = threadIdx.x & 31;
    const float* p = kall + (size_t)row * HID;
    float4 a0 = *(const float4*)(p + ln * 8);
    float4 a1 = *(const float4*)(p + ln * 8 + 4);
    float4 b0 = *(const float4*)(p + HALF_ + ln * 8);
    float4 b1 = *(const float4*)(p + HALF_ + ln * 8 + 4);
    float s0 = a0.x*a0.x + a0.y*a0.y + a0.z*a0.z + a0.w*a0.w
             + a1.x*a1.x + a1.y*a1.y + a1.z*a1.z + a1.w*a1.w;
    float s1 = b0.x*b0.x + b0.y*b0.y + b0.z*b0.z + b0.w*b0.w
             + b1.x*b1.x + b1.y*b1.y + b1.z*b1.z + b1.w*b1.w;
#pragma unroll
    for (int o = 16; o; o >>= 1) {
        s0 += __shfl_xor_sync(0xffffffffu, s0, o);
        s1 += __shfl_xor_sync(0xffffffffu, s1, o);
    }
    if (ln == 0) {
        invd[(size_t)row * 2 + 0] = 1.f / (s0 + 1e-6f);
        invd[(size_t)row * 2 + 1] = 1.f / (s1 + 1e-6f);
    }
}

// ============================================================
// Backward vector scan (one warp per (batch, half) chain).
// ============================================================
__global__ void __launch_bounds__(32) scan_k(const float* __restrict__ kall,
                                             const float* __restrict__ invd,
                                             float* __restrict__ cbuf)
{
    const int chain = blockIdx.x;
    const int b = chain >> 1, wh = chain & 1;
    const int ln = threadIdx.x;
    const float* base = kall + (size_t)b * SEQL * HID + wh * HALF_ + ln * 8;

    float u[8], acc[8];
    {
        float4 q0 = *(const float4*)(base + (size_t)(SEQL - 1) * HID);
        float4 q1 = *(const float4*)(base + (size_t)(SEQL - 1) * HID + 4);
        u[0]=q0.x; u[1]=q0.y; u[2]=q0.z; u[3]=q0.w;
        u[4]=q1.x; u[5]=q1.y; u[6]=q1.z; u[7]=q1.w;
    }
#pragma unroll
    for (int j = 0; j < 8; j++) acc[j] = 0.f;

    float kc[8];
    {
        float4 t0 = *(const float4*)(base + (size_t)(SEQL - 2) * HID);
        float4 t1 = *(const float4*)(base + (size_t)(SEQL - 2) * HID + 4);
        kc[0]=t0.x; kc[1]=t0.y; kc[2]=t0.z; kc[3]=t0.w;
        kc[4]=t1.x; kc[5]=t1.y; kc[6]=t1.z; kc[7]=t1.w;
    }

    for (int t = SEQL - 2; t >= 0; --t) {
        float kn[8] = {0,0,0,0,0,0,0,0};
        if (t > 0) {
            float4 t0 = *(const float4*)(base + (size_t)(t - 1) * HID);
            float4 t1 = *(const float4*)(base + (size_t)(t - 1) * HID + 4);
            kn[0]=t0.x; kn[1]=t0.y; kn[2]=t0.z; kn[3]=t0.w;
            kn[4]=t1.x; kn[5]=t1.y; kn[6]=t1.z; kn[7]=t1.w;
        }
        const float id = invd[((size_t)b * SEQL + t) * 2 + wh];
        float p0 = u[0]*kc[0] + u[1]*kc[1];
        float p1 = u[2]*kc[2] + u[3]*kc[3];
        float p2 = u[4]*kc[4] + u[5]*kc[5];
        float p3 = u[6]*kc[6] + u[7]*kc[7];
        float s = (p0 + p1) + (p2 + p3);
#pragma unroll
        for (int o = 16; o; o >>= 1) s += __shfl_xor_sync(0xffffffffu, s, o);
        const float w = wh ? (float)(t + 1) * (1.f / 1024.f) : 1.f;
        const float ws = w * s;
        const float us = ws * id;
#pragma unroll
        for (int j = 0; j < 8; j++) {
            acc[j] += ws * kc[j];
            u[j]   -= us * kc[j];
        }
#pragma unroll
        for (int j = 0; j < 8; j++) kc[j] = kn[j];
    }
    float4 o0 = make_float4(acc[0], acc[1], acc[2], acc[3]);
    float4 o1 = make_float4(acc[4], acc[5], acc[6], acc[7]);
    *(float4*)(cbuf + (size_t)b * HID + wh * HALF_ + ln * 8) = o0;
    *(float4*)(cbuf + (size_t)b * HID + wh * HALF_ + ln * 8 + 4) = o1;
}

// ============================================================
extern "C" void kernel_launch(void* const* d_in, const int* in_sizes, int n_in,
                              void* d_out, int out_size)
{
    const int*   seq   = (const int*)d_in[0];
    const float* embed = (const float*)d_in[1];
    const float* w1    = (const float*)d_in[2];
    const float* b1    = (const float*)d_in[3];
    const float* w2    = (const float*)d_in[4];
    const float* b2    = (const float*)d_in[5];
    const float* lng   = (const float*)d_in[6];
    const float* lnb   = (const float*)d_in[7];
    const float* sw    = (const float*)d_in[8];
    const float* sb    = (const float*)d_in[9];
    const float* ew    = (const float*)d_in[10];
    const float* eb    = (const float*)d_in[11];
    const float* ow    = (const float*)d_in[12];
    const float* ob    = (const float*)d_in[13];
    float* out = (float*)d_out;

    static bool init = false;
    static bf16 *ah, *al, *h1h, *h1l, *hh, *hl, *w1h, *w1l, *w2h, *w2l,
                *wph, *wpl, *owh, *owl, *ch, *cl;
    static float *xb, *kb, *bp, *ivd, *cb;
    if (!init) {
        cudaGetSymbolAddress((void**)&ah,  g_ah);   cudaGetSymbolAddress((void**)&al,  g_al);
        cudaGetSymbolAddress((void**)&h1h, g_h1h);  cudaGetSymbolAddress((void**)&h1l, g_h1l);
        cudaGetSymbolAddress((void**)&hh,  g_hh);   cudaGetSymbolAddress((void**)&hl,  g_hl);
        cudaGetSymbolAddress((void**)&w1h, g_w1h);  cudaGetSymbolAddress((void**)&w1l, g_w1l);
        cudaGetSymbolAddress((void**)&w2h, g_w2h);  cudaGetSymbolAddress((void**)&w2l, g_w2l);
        cudaGetSymbolAddress((void**)&wph, g_wph);  cudaGetSymbolAddress((void**)&wpl, g_wpl);
        cudaGetSymbolAddress((void**)&owh, g_owh);  cudaGetSymbolAddress((void**)&owl, g_owl);
        cudaGetSymbolAddress((void**)&ch,  g_ch);   cudaGetSymbolAddress((void**)&cl,  g_cl);
        cudaGetSymbolAddress((void**)&xb,  g_x);
        cudaGetSymbolAddress((void**)&kb,  g_k);
        cudaGetSymbolAddress((void**)&bp,  g_bproj);
        cudaGetSymbolAddress((void**)&ivd, g_invd);
        cudaGetSymbolAddress((void**)&cb,  g_c);
        cudaFuncSetAttribute(mma_gemm<0>, cudaFuncAttributeMaxDynamicSharedMemorySize, GSMEM);
        cudaFuncSetAttribute(mma_gemm<1>, cudaFuncAttributeMaxDynamicSharedMemorySize, GSMEM);
        cudaFuncSetAttribute(mma_gemm<2>, cudaFuncAttributeMaxDynamicSharedMemorySize, GSMEM);
        init = true;
    }

    // weight transpose + split (B operands are [N,K] K-major)
    tsplit_k<<<dim3(FF / 32, HID / 32), 256>>>(w1, HID, FF, w1h, w1l);
    tsplit_k<<<dim3(HID / 32, FF / 32), 256>>>(w2, FF, HID, w2h, w2l);
    tsplit_k<<<dim3(HALF_ / 32, HID / 32), 256>>>(sw, HID, HALF_, wph, wpl);
    tsplit_k<<<dim3(HALF_ / 32, HID / 32), 256>>>(ew, HID, HALF_, wph + (size_t)HALF_ * HID,
                                                  wpl + (size_t)HALF_ * HID);
    tsplit_k<<<dim3(VOC / 32, HID / 32), 256>>>(ow, HID, VOC, owh, owl);
    bpack_k<<<2, 256>>>(sb, eb);

    // A operand for GEMM1: gathered embeddings, split
    gsplit_k<<<TOK * 64 / 256, 256>>>(seq, embed, ah, al);

    // GEMM1: relu(e @ w1 + b1) -> h1 (bf16 hi/lo)   [65536 x 1024, K=512]
    mma_gemm<0><<<dim3(FF / 128, TOK / 128), 256, GSMEM>>>(
        TOK, FF, HID, ah, al, w1h, w1l, b1, nullptr, h1h, h1l, nullptr, nullptr);

    // GEMM2: x = h1 @ w2 + b2 + e  -> fp32          [65536 x 512, K=1024]
    mma_gemm<1><<<dim3(HID / 128, TOK / 128), 256, GSMEM>>>(
        TOK, HID, FF, h1h, h1l, w2h, w2l, b2, xb, nullptr, nullptr, seq, embed);

    // LayerNorm -> h (bf16 hi/lo)
    ln_split_k<<<TOK / 8, 256>>>(xb, lng, lnb, hh, hl);

    // GEMM3: k = h @ [sem|epi] + bias -> fp32       [65536 x 512, K=512]
    mma_gemm<2><<<dim3(HID / 128, TOK / 128), 256, GSMEM>>>(
        TOK, HID, HID, hh, hl, wph, wpl, bp, kb, nullptr, nullptr, nullptr, nullptr);

    // norms + backward scan
    norms_k<<<TOK / 8, 256>>>(kb, ivd);
    scan_k<<<128, 32>>>(kb, ivd, cb);

    // split c for final GEMM
    csplit_k<<<BATCH * HID / 256, 256>>>(cb, ch, cl);

    // GEMM4: out = c @ out_w + out_b                [64 x 32000, K=512]
    mma_gemm<2><<<dim3(VOC / 128, 1), 256, GSMEM>>>(
        BATCH, VOC, HID, ch, cl, owh, owl, ob, out, nullptr, nullptr, nullptr, nullptr);
}

// round 7
// speedup vs baseline: 3.6921x; 1.2373x over previous
#include <cuda_runtime.h>
#include <cuda_fp16.h>
#include <cstdint>

// Problem constants
#define TOK   65536      // B*L
#define BATCH 64
#define SEQL  1024
#define HID   512
#define FF    1024
#define HALF_ 256
#define VOC   32000

typedef __half half_t;

__device__ __forceinline__ uint32_t smem_u32(const void* p) {
    uint32_t a;
    asm("{ .reg .u64 t; cvta.to.shared.u64 t, %1; cvt.u32.u64 %0, t; }" : "=r"(a) : "l"(p));
    return a;
}
#define SW128(o) ((o) ^ (((o) >> 3) & 0x70))

__device__ __forceinline__ void ldsm4(uint32_t* r, uint32_t a) {
    asm volatile("ldmatrix.sync.aligned.m8n8.x4.shared.b16 {%0,%1,%2,%3}, [%4];"
        : "=r"(r[0]), "=r"(r[1]), "=r"(r[2]), "=r"(r[3]) : "r"(a));
}
__device__ __forceinline__ void mma16816(float* c, const uint32_t* a, const uint32_t* b) {
    asm volatile("mma.sync.aligned.m16n8k16.row.col.f32.f16.f16.f32 "
        "{%0,%1,%2,%3}, {%4,%5,%6,%7}, {%8,%9}, {%0,%1,%2,%3};"
        : "+f"(c[0]), "+f"(c[1]), "+f"(c[2]), "+f"(c[3])
        : "r"(a[0]), "r"(a[1]), "r"(a[2]), "r"(a[3]), "r"(b[0]), "r"(b[1]));
}
__device__ __forceinline__ void cp16(uint32_t dst, const void* src, bool pred) {
    const int sz = pred ? 16 : 0;
    asm volatile("cp.async.cg.shared.global [%0], [%1], 16, %2;"
        :: "r"(dst), "l"(src), "r"(sz) : "memory");
}
#define CP_COMMIT() asm volatile("cp.async.commit_group;" ::: "memory")
template<int N>
__device__ __forceinline__ void cp_wait() {
    asm volatile("cp.async.wait_group %0;" :: "n"(N) : "memory");
}

__device__ __forceinline__ void split2h(float x, half_t& h, half_t& l) {
    h = __float2half_rn(x);
    l = __float2half_rn(x - __half2float(h));
}

// -------- scratch (device globals) --------
__device__ half_t g_ah[(size_t)TOK * HID],  g_al[(size_t)TOK * HID];
__device__ half_t g_h1h[(size_t)TOK * FF],  g_h1l[(size_t)TOK * FF];
__device__ half_t g_hh[(size_t)TOK * HID],  g_hl[(size_t)TOK * HID];
__device__ float  g_x[(size_t)TOK * HID];
__device__ float  g_k[(size_t)TOK * HID];
__device__ half_t g_w1h[(size_t)FF * HID];
__device__ half_t g_w2h[(size_t)HID * FF];
__device__ half_t g_wph[(size_t)HID * HID];
__device__ half_t g_owh[(size_t)VOC * HID];
__device__ float  g_bproj[HID];
__device__ float  g_invd[(size_t)TOK * 2];
__device__ float  g_c[BATCH * HID];
__device__ half_t g_ch[BATCH * HID], g_cl[BATCH * HID];

// ============================================================
// mma.sync fp16 2-pass GEMM, cp.async 4-stage pipeline.
// C[M,N] = A[M,K] @ B^T;  A [M,K] K-major hi/lo fp16, B [N,K] K-major single fp16.
// C = Ah*B + Al*B  (A hi/lo split; B single fp16, 11-bit mantissa).
// 128x128 CTA tile, BK=32, 256 threads (8 warps, 64x32 each).
// A smem rows: 128B = [hi 64B | lo 64B]; B smem: two 64B rows packed per
// 128B line: off(n,k) = (n>>1)*128 + (n&1)*64 + k*2, SW128 (conflict-free).
// Stage = 16KB A + 8KB B = 24KB; 4 stages; one __syncthreads per chunk.
// EPI: 0 = relu(acc+bias) -> split fp16; 1 = acc+bias+embed[seq[m]] -> f32;
//      2 = acc+bias -> f32.
// ============================================================
#define ASTAGE 16384
#define GSTAGE 24576
#define NSTAGE 4
#define GSMEM  (NSTAGE * GSTAGE)

template<int EPI>
__global__ void __launch_bounds__(256, 2) mma_gemm(
    int Mrows, int N, int K,
    const half_t* __restrict__ Ah, const half_t* __restrict__ Al,
    const half_t* __restrict__ Bh,
    const float* __restrict__ bias,
    float* __restrict__ Cf, half_t* __restrict__ Chi, half_t* __restrict__ Clo,
    const int* __restrict__ seq, const float* __restrict__ embed)
{
    extern __shared__ __align__(1024) char smem[];
    const uint32_t sbase = smem_u32(smem);
    const int tid = threadIdx.x;
    const int bm = blockIdx.y * 128;
    const int bn = blockIdx.x * 128;
    const int wid = tid >> 5, lane = tid & 31;
    const int wm = (wid >> 2) * 64;     // warp row offset (0 / 64)
    const int wn = (wid & 3) * 32;      // warp col offset (0..96)
    const bool mguard = (Mrows & 127) != 0;

    // loader mapping (A): 2 threads per row, each 2x16B per half
    const int lrow = tid >> 1;
    const int lw = (tid & 1) * 2;
    const int am = bm + lrow;
    const bool av = !mguard || (am < Mrows);
    const size_t aoff = (size_t)(av ? am : 0) * K;
    const size_t boff = (size_t)(bn + lrow) * K;
    // B smem line base for loader row
    const uint32_t bline = (uint32_t)((lrow >> 1) * 128 + (lrow & 1) * 64);

    // A ldmatrix lane addressing (m16 x k16 per x4)
    const int a_mi = lane >> 3;
    const int a_row = (lane & 7) + (a_mi & 1) * 8;
    const int a_kb = (a_mi >> 1) * 16;
    // B ldmatrix lane addressing (2 n8 tiles x 2 k-halves per x4)
    const int b_g = lane >> 3;
    const int b_row = lane & 7;
    const int b_nt = b_g >> 1;
    const int b_kh = (b_g & 1) * 16;

    float c[16][4];
#pragma unroll
    for (int i = 0; i < 16; i++)
#pragma unroll
        for (int j = 0; j < 4; j++) c[i][j] = 0.f;

    const int NCH = K >> 5;

    auto load_stage = [&](int s, int k0) {
        const uint32_t sA = sbase + s * GSTAGE;
        const uint32_t sB = sA + ASTAGE;
#pragma unroll
        for (int it = 0; it < 2; it++) {
            const int word = lw + it;              // 0..3
            const uint32_t soh = SW128((uint32_t)(lrow * 128 + word * 16));
            const uint32_t sol = SW128((uint32_t)(lrow * 128 + 64 + word * 16));
            const size_t ko = (size_t)(k0 + word * 8);
            cp16(sA + soh, Ah + aoff + ko, av);
            cp16(sA + sol, Al + aoff + ko, av);
            // B: word covers fp16 elems word*8..word*8+7 of BK=32
            const uint32_t sob = SW128(bline + word * 16);
            cp16(sB + sob, Bh + boff + ko, true);
        }
    };

    load_stage(0, 0);
    CP_COMMIT();
    load_stage(1, 32);
    CP_COMMIT();
    load_stage(2, 64);
    CP_COMMIT();

    int stage = 0;
    for (int ch = 0; ch < NCH; ch++) {
        cp_wait<2>();
        __syncthreads();
        if (ch + 3 < NCH) {
            int ns = stage + 3; if (ns >= NSTAGE) ns -= NSTAGE;
            load_stage(ns, (ch + 3) * 32);
        }
        CP_COMMIT();   // always commit (possibly empty) to keep group accounting
        const uint32_t sAu = sbase + stage * GSTAGE;
        const uint32_t sBu = sAu + ASTAGE;
        // ---- compute: 2 k16 steps, 2 passes each ----
#pragma unroll
        for (int k16 = 0; k16 < 2; k16++) {
            const int kb = k16 * 32;
            uint32_t bfrag[2][4];
#pragma unroll
            for (int p = 0; p < 2; p++) {
                const int n = wn + (p * 2 + b_nt) * 8 + b_row;
                const uint32_t rb = (uint32_t)((n >> 1) * 128 + (n & 1) * 64);
                ldsm4(bfrag[p], sBu + SW128(rb + kb + b_kh));
            }
            uint32_t a[4][4];
#pragma unroll
            for (int mt = 0; mt < 4; mt++)
                ldsm4(a[mt], sAu + SW128((uint32_t)((wm + mt * 16 + a_row) * 128) + kb + a_kb));
#pragma unroll
            for (int mt = 0; mt < 4; mt++)
#pragma unroll
                for (int nt = 0; nt < 4; nt++)
                    mma16816(c[mt * 4 + nt], a[mt], &bfrag[nt >> 1][(nt & 1) * 2]);
            // lo(A) pass
#pragma unroll
            for (int mt = 0; mt < 4; mt++)
                ldsm4(a[mt], sAu + SW128((uint32_t)((wm + mt * 16 + a_row) * 128) + 64 + kb + a_kb));
#pragma unroll
            for (int mt = 0; mt < 4; mt++)
#pragma unroll
                for (int nt = 0; nt < 4; nt++)
                    mma16816(c[mt * 4 + nt], a[mt], &bfrag[nt >> 1][(nt & 1) * 2]);
        }
        if (++stage >= NSTAGE) stage = 0;
    }

    // ---- epilogue ----
    const int mrow = lane >> 2;
    const int mcol = (lane & 3) * 2;
#pragma unroll
    for (int mt = 0; mt < 4; mt++) {
        const int r0 = bm + wm + mt * 16 + mrow;
        const int r1 = r0 + 8;
        const bool v0 = !mguard || (r0 < Mrows);
        const bool v1 = !mguard || (r1 < Mrows);
        const float* e0 = nullptr;
        const float* e1 = nullptr;
        if (EPI == 1) {
            if (v0) e0 = embed + (size_t)seq[r0] * HID;
            if (v1) e1 = embed + (size_t)seq[r1] * HID;
        }
#pragma unroll
        for (int nt = 0; nt < 4; nt++) {
            const int col = bn + wn + nt * 8 + mcol;
            float* cc = c[mt * 4 + nt];
            const float b0v = bias[col], b1v = bias[col + 1];
            float x0 = cc[0] + b0v, x1 = cc[1] + b1v;
            float x2 = cc[2] + b0v, x3 = cc[3] + b1v;
            if (EPI == 0) {
                x0 = fmaxf(x0, 0.f); x1 = fmaxf(x1, 0.f);
                x2 = fmaxf(x2, 0.f); x3 = fmaxf(x3, 0.f);
                half_t h0, l0, h1, l1;
                if (v0) {
                    split2h(x0, h0, l0); split2h(x1, h1, l1);
                    __half2 ph; ph.x = h0; ph.y = h1;
                    __half2 pl; pl.x = l0; pl.y = l1;
                    *(__half2*)(Chi + (size_t)r0 * N + col) = ph;
                    *(__half2*)(Clo + (size_t)r0 * N + col) = pl;
                }
                if (v1) {
                    split2h(x2, h0, l0); split2h(x3, h1, l1);
                    __half2 ph; ph.x = h0; ph.y = h1;
                    __half2 pl; pl.x = l0; pl.y = l1;
                    *(__half2*)(Chi + (size_t)r1 * N + col) = ph;
                    *(__half2*)(Clo + (size_t)r1 * N + col) = pl;
                }
            } else {
                if (EPI == 1) {
                    if (v0) { x0 += e0[col]; x1 += e0[col + 1]; }
                    if (v1) { x2 += e1[col]; x3 += e1[col + 1]; }
                }
                if (v0) *(float2*)(Cf + (size_t)r0 * N + col) = make_float2(x0, x1);
                if (v1) *(float2*)(Cf + (size_t)r1 * N + col) = make_float2(x2, x3);
            }
        }
    }
}

// ============================================================
// gather + split:  Ahi/Alo[m] = split(embed[seq[m]])  (fp16)
// ============================================================
__global__ void __launch_bounds__(256) gsplit_k(const int* __restrict__ seq,
                                                const float* __restrict__ embed,
                                                half_t* __restrict__ hi, half_t* __restrict__ lo)
{
    const size_t idx = (size_t)blockIdx.x * 256 + threadIdx.x;   // TOK*64
    const int t = (int)(idx >> 6), c = (int)(idx & 63) * 8;
    const float* p = embed + (size_t)seq[t] * HID + c;
    float4 a = *(const float4*)p;
    float4 b = *(const float4*)(p + 4);
    float vv[8] = {a.x, a.y, a.z, a.w, b.x, b.y, b.z, b.w};
    const size_t ob = (size_t)t * HID + c;
#pragma unroll
    for (int j = 0; j < 8; j += 2) {
        half_t h0, l0, h1, l1;
        split2h(vv[j], h0, l0);
        split2h(vv[j + 1], h1, l1);
        __half2 ph; ph.x = h0; ph.y = h1;
        __half2 pl; pl.x = l0; pl.y = l1;
        *(__half2*)(hi + ob + j) = ph;
        *(__half2*)(lo + ob + j) = pl;
    }
}

// ============================================================
// Tiled transpose + round: W[K,N] fp32 -> out[N,K] single fp16.
// ============================================================
__global__ void __launch_bounds__(256) tsplit1_k(const float* __restrict__ W, int K, int N,
                                                 half_t* __restrict__ ht)
{
    __shared__ float t[32][33];
    const int tx = threadIdx.x & 31, ty = threadIdx.x >> 5;
    const int n0 = blockIdx.x * 32, k0 = blockIdx.y * 32;
#pragma unroll
    for (int i = 0; i < 4; i++)
        t[ty + 8 * i][tx] = W[(size_t)(k0 + ty + 8 * i) * N + n0 + tx];
    __syncthreads();
#pragma unroll
    for (int i = 0; i < 4; i++) {
        const size_t o = (size_t)(n0 + ty + 8 * i) * K + k0 + tx;
        ht[o] = __float2half_rn(t[tx][ty + 8 * i]);
    }
}

// ============================================================
// LayerNorm (warp per row) + split output to fp16 hi/lo.
// ============================================================
__global__ void __launch_bounds__(256) ln_split_k(const float* __restrict__ x,
                                                  const float* __restrict__ g,
                                                  const float* __restrict__ b,
                                                  half_t* __restrict__ hh, half_t* __restrict__ hl)
{
    const int row = blockIdx.x * 8 + (threadIdx.x >> 5);
    const int ln = threadIdx.x & 31;
    const float* xr = x + (size_t)row * HID + ln * 16;
    float v[16];
    *(float4*)&v[0]  = ((const float4*)xr)[0];
    *(float4*)&v[4]  = ((const float4*)xr)[1];
    *(float4*)&v[8]  = ((const float4*)xr)[2];
    *(float4*)&v[12] = ((const float4*)xr)[3];
    float s = 0.f;
#pragma unroll
    for (int j = 0; j < 16; j++) s += v[j];
#pragma unroll
    for (int o = 16; o; o >>= 1) s += __shfl_xor_sync(0xffffffffu, s, o);
    const float mean = s * (1.f / 512.f);
    float q = 0.f;
#pragma unroll
    for (int j = 0; j < 16; j++) { float d = v[j] - mean; q += d * d; }
#pragma unroll
    for (int o = 16; o; o >>= 1) q += __shfl_xor_sync(0xffffffffu, q, o);
    const float r = rsqrtf(q * (1.f / 512.f) + 1e-5f);
    const size_t ob = (size_t)row * HID + ln * 16;
#pragma unroll
    for (int j = 0; j < 16; j += 2) {
        const int c0 = ln * 16 + j;
        float y0 = (v[j] - mean) * r * g[c0] + b[c0];
        float y1 = (v[j + 1] - mean) * r * g[c0 + 1] + b[c0 + 1];
        half_t h0, l0, h1, l1;
        split2h(y0, h0, l0);
        split2h(y1, h1, l1);
        __half2 ph; ph.x = h0; ph.y = h1;
        __half2 pl; pl.x = l0; pl.y = l1;
        *(__half2*)(hh + ob + j) = ph;
        *(__half2*)(hl + ob + j) = pl;
    }
}

// ============================================================
__global__ void bpack_k(const float* __restrict__ sb, const float* __restrict__ eb)
{
    const int i = blockIdx.x * 256 + threadIdx.x;
    if (i < HID) g_bproj[i] = (i < HALF_) ? sb[i] : eb[i - HALF_];
}

__global__ void __launch_bounds__(256) csplit_k(const float* __restrict__ c,
                                                half_t* __restrict__ h, half_t* __restrict__ l)
{
    const int i = blockIdx.x * 256 + threadIdx.x;   // 32768
    half_t hh, ll;
    split2h(c[i], hh, ll);
    h[i] = hh;
    l[i] = ll;
}

// ============================================================
// inv_d = 1/(||k||^2 + 1e-6); one warp per token.
// ============================================================
__global__ void __launch_bounds__(256) norms_k(const float* __restrict__ kall,
                                               float* __restrict__ invd)
{
    const int row = blockIdx.x * 8 + (threadIdx.x >> 5);
    const int ln = threadIdx.x & 31;
    const float* p = kall + (size_t)row * HID;
    float4 a0 = *(const float4*)(p + ln * 8);
    float4 a1 = *(const float4*)(p + ln * 8 + 4);
    float4 b0 = *(const float4*)(p + HALF_ + ln * 8);
    float4 b1 = *(const float4*)(p + HALF_ + ln * 8 + 4);
    float s0 = a0.x*a0.x + a0.y*a0.y + a0.z*a0.z + a0.w*a0.w
             + a1.x*a1.x + a1.y*a1.y + a1.z*a1.z + a1.w*a1.w;
    float s1 = b0.x*b0.x + b0.y*b0.y + b0.z*b0.z + b0.w*b0.w
             + b1.x*b1.x + b1.y*b1.y + b1.z*b1.z + b1.w*b1.w;
#pragma unroll
    for (int o = 16; o; o >>= 1) {
        s0 += __shfl_xor_sync(0xffffffffu, s0, o);
        s1 += __shfl_xor_sync(0xffffffffu, s1, o);
    }
    if (ln == 0) {
        invd[(size_t)row * 2 + 0] = 1.f / (s0 + 1e-6f);
        invd[(size_t)row * 2 + 1] = 1.f / (s1 + 1e-6f);
    }
}

// ============================================================
// Backward vector scan (one warp per (batch, half) chain).
// ============================================================
__global__ void __launch_bounds__(32) scan_k(const float* __restrict__ kall,
                                             const float* __restrict__ invd,
                                             float* __restrict__ cbuf)
{
    const int chain = blockIdx.x;
    const int b = chain >> 1, wh = chain & 1;
    const int ln = threadIdx.x;
    const float* base = kall + (size_t)b * SEQL * HID + wh * HALF_ + ln * 8;

    float u[8], acc[8];
    {
        float4 q0 = *(const float4*)(base + (size_t)(SEQL - 1) * HID);
        float4 q1 = *(const float4*)(base + (size_t)(SEQL - 1) * HID + 4);
        u[0]=q0.x; u[1]=q0.y; u[2]=q0.z; u[3]=q0.w;
        u[4]=q1.x; u[5]=q1.y; u[6]=q1.z; u[7]=q1.w;
    }
#pragma unroll
    for (int j = 0; j < 8; j++) acc[j] = 0.f;

    float kc[8];
    {
        float4 t0 = *(const float4*)(base + (size_t)(SEQL - 2) * HID);
        float4 t1 = *(const float4*)(base + (size_t)(SEQL - 2) * HID + 4);
        kc[0]=t0.x; kc[1]=t0.y; kc[2]=t0.z; kc[3]=t0.w;
        kc[4]=t1.x; kc[5]=t1.y; kc[6]=t1.z; kc[7]=t1.w;
    }

    for (int t = SEQL - 2; t >= 0; --t) {
        float kn[8] = {0,0,0,0,0,0,0,0};
        if (t > 0) {
            float4 t0 = *(const float4*)(base + (size_t)(t - 1) * HID);
            float4 t1 = *(const float4*)(base + (size_t)(t - 1) * HID + 4);
            kn[0]=t0.x; kn[1]=t0.y; kn[2]=t0.z; kn[3]=t0.w;
            kn[4]=t1.x; kn[5]=t1.y; kn[6]=t1.z; kn[7]=t1.w;
        }
        const float id = invd[((size_t)b * SEQL + t) * 2 + wh];
        float p0 = u[0]*kc[0] + u[1]*kc[1];
        float p1 = u[2]*kc[2] + u[3]*kc[3];
        float p2 = u[4]*kc[4] + u[5]*kc[5];
        float p3 = u[6]*kc[6] + u[7]*kc[7];
        float s = (p0 + p1) + (p2 + p3);
#pragma unroll
        for (int o = 16; o; o >>= 1) s += __shfl_xor_sync(0xffffffffu, s, o);
        const float w = wh ? (float)(t + 1) * (1.f / 1024.f) : 1.f;
        const float ws = w * s;
        const float us = ws * id;
#pragma unroll
        for (int j = 0; j < 8; j++) {
            acc[j] += ws * kc[j];
            u[j]   -= us * kc[j];
        }
#pragma unroll
        for (int j = 0; j < 8; j++) kc[j] = kn[j];
    }
    float4 o0 = make_float4(acc[0], acc[1], acc[2], acc[3]);
    float4 o1 = make_float4(acc[4], acc[5], acc[6], acc[7]);
    *(float4*)(cbuf + (size_t)b * HID + wh * HALF_ + ln * 8) = o0;
    *(float4*)(cbuf + (size_t)b * HID + wh * HALF_ + ln * 8 + 4) = o1;
}

// ============================================================
extern "C" void kernel_launch(void* const* d_in, const int* in_sizes, int n_in,
                              void* d_out, int out_size)
{
    const int*   seq   = (const int*)d_in[0];
    const float* embed = (const float*)d_in[1];
    const float* w1    = (const float*)d_in[2];
    const float* b1    = (const float*)d_in[3];
    const float* w2    = (const float*)d_in[4];
    const float* b2    = (const float*)d_in[5];
    const float* lng   = (const float*)d_in[6];
    const float* lnb   = (const float*)d_in[7];
    const float* sw    = (const float*)d_in[8];
    const float* sb    = (const float*)d_in[9];
    const float* ew    = (const float*)d_in[10];
    const float* eb    = (const float*)d_in[11];
    const float* ow    = (const float*)d_in[12];
    const float* ob    = (const float*)d_in[13];
    float* out = (float*)d_out;

    static bool init = false;
    static half_t *ah, *al, *h1h, *h1l, *hh, *hl, *w1h, *w2h, *wph, *owh, *ch, *cl;
    static float *xb, *kb, *bp, *ivd, *cb;
    if (!init) {
        cudaGetSymbolAddress((void**)&ah,  g_ah);   cudaGetSymbolAddress((void**)&al,  g_al);
        cudaGetSymbolAddress((void**)&h1h, g_h1h);  cudaGetSymbolAddress((void**)&h1l, g_h1l);
        cudaGetSymbolAddress((void**)&hh,  g_hh);   cudaGetSymbolAddress((void**)&hl,  g_hl);
        cudaGetSymbolAddress((void**)&w1h, g_w1h);
        cudaGetSymbolAddress((void**)&w2h, g_w2h);
        cudaGetSymbolAddress((void**)&wph, g_wph);
        cudaGetSymbolAddress((void**)&owh, g_owh);
        cudaGetSymbolAddress((void**)&ch,  g_ch);   cudaGetSymbolAddress((void**)&cl,  g_cl);
        cudaGetSymbolAddress((void**)&xb,  g_x);
        cudaGetSymbolAddress((void**)&kb,  g_k);
        cudaGetSymbolAddress((void**)&bp,  g_bproj);
        cudaGetSymbolAddress((void**)&ivd, g_invd);
        cudaGetSymbolAddress((void**)&cb,  g_c);
        cudaFuncSetAttribute(mma_gemm<0>, cudaFuncAttributeMaxDynamicSharedMemorySize, GSMEM);
        cudaFuncSetAttribute(mma_gemm<1>, cudaFuncAttributeMaxDynamicSharedMemorySize, GSMEM);
        cudaFuncSetAttribute(mma_gemm<2>, cudaFuncAttributeMaxDynamicSharedMemorySize, GSMEM);
        init = true;
    }

    // weight transpose + fp16 round (B operands are [N,K] K-major, single fp16)
    tsplit1_k<<<dim3(FF / 32, HID / 32), 256>>>(w1, HID, FF, w1h);
    tsplit1_k<<<dim3(HID / 32, FF / 32), 256>>>(w2, FF, HID, w2h);
    tsplit1_k<<<dim3(HALF_ / 32, HID / 32), 256>>>(sw, HID, HALF_, wph);
    tsplit1_k<<<dim3(HALF_ / 32, HID / 32), 256>>>(ew, HID, HALF_, wph + (size_t)HALF_ * HID);
    tsplit1_k<<<dim3(VOC / 32, HID / 32), 256>>>(ow, HID, VOC, owh);
    bpack_k<<<2, 256>>>(sb, eb);

    // A operand for GEMM1: gathered embeddings, split fp16
    gsplit_k<<<TOK * 64 / 256, 256>>>(seq, embed, ah, al);

    // GEMM1: relu(e @ w1 + b1) -> h1 (fp16 hi/lo)   [65536 x 1024, K=512]
    mma_gemm<0><<<dim3(FF / 128, TOK / 128), 256, GSMEM>>>(
        TOK, FF, HID, ah, al, w1h, b1, nullptr, h1h, h1l, nullptr, nullptr);

    // GEMM2: x = h1 @ w2 + b2 + e  -> fp32          [65536 x 512, K=1024]
    mma_gemm<1><<<dim3(HID / 128, TOK / 128), 256, GSMEM>>>(
        TOK, HID, FF, h1h, h1l, w2h, b2, xb, nullptr, nullptr, seq, embed);

    // LayerNorm -> h (fp16 hi/lo)
    ln_split_k<<<TOK / 8, 256>>>(xb, lng, lnb, hh, hl);

    // GEMM3: k = h @ [sem|epi] + bias -> fp32       [65536 x 512, K=512]
    mma_gemm<2><<<dim3(HID / 128, TOK / 128), 256, GSMEM>>>(
        TOK, HID, HID, hh, hl, wph, bp, kb, nullptr, nullptr, nullptr, nullptr);

    // norms + backward scan
    norms_k<<<TOK / 8, 256>>>(kb, ivd);
    scan_k<<<128, 32>>>(kb, ivd, cb);

    // split c for final GEMM
    csplit_k<<<BATCH * HID / 256, 256>>>(cb, ch, cl);

    // GEMM4: out = c @ out_w + out_b                [64 x 32000, K=512]
    mma_gemm<2><<<dim3(VOC / 128, 1), 256, GSMEM>>>(
        BATCH, VOC, HID, ch, cl, owh, ob, out, nullptr, nullptr, nullptr, nullptr);
}